// round 14
// baseline (speedup 1.0000x reference)
#include <cuda_runtime.h>
#include <cuda_bf16.h>
#include <math.h>
#include <stdint.h>

// ---------------- static scratch (no allocations allowed) ----------------
#define MAXN   50048            // padded (391*128)
#define MAXE   800000

__device__ float g_x0[MAXN * 128];
__device__ float g_x1[MAXN * 128];
__device__ __nv_bfloat16 g_Ah[(size_t)MAXN * 768];   // agg hi split (bf16)
__device__ __nv_bfloat16 g_Al[(size_t)MAXN * 768];   // agg lo split
__device__ float g_t[MAXN * 8];          // [N,6] padded to 8
__device__ __nv_bfloat16 g_Bh[4][768 * 128];  // B split hi: [l][n*768+k]
__device__ __nv_bfloat16 g_Bl[4][768 * 128];  // B split lo
__device__ int   g_deg[MAXN];
__device__ int   g_off[MAXN + 1];
__device__ int   g_cur[MAXN];
__device__ int   g_src[MAXE];
__device__ int   g_dst[MAXE];

// ---------------- helpers ----------------
__device__ __forceinline__ uint32_t smem_u32(const void* p) {
    uint32_t a;
    asm("{ .reg .u64 t; cvta.to.shared.u64 t, %1; cvt.u32.u64 %0, t; }" : "=r"(a) : "l"(p));
    return a;
}
__device__ __forceinline__ void cpa16(uint32_t dst, const void* src) {
    asm volatile("cp.async.cg.shared.global [%0], [%1], 16;" :: "r"(dst), "l"(src));
}
#define CP_COMMIT() asm volatile("cp.async.commit_group;")
#define LDMX4(r, addr)                                                          \
    asm volatile("ldmatrix.sync.aligned.m8n8.x4.shared.b16 {%0,%1,%2,%3}, [%4];"\
        : "=r"((r)[0]), "=r"((r)[1]), "=r"((r)[2]), "=r"((r)[3]) : "r"(addr))
#define MMA_BF16(d, a, b0, b1)                                                  \
    asm volatile("mma.sync.aligned.m16n8k16.row.col.f32.bf16.bf16.f32 "         \
        "{%0,%1,%2,%3}, {%4,%5,%6,%7}, {%8,%9}, {%0,%1,%2,%3};"                 \
        : "+f"((d)[0]), "+f"((d)[1]), "+f"((d)[2]), "+f"((d)[3])                \
        : "r"((a)[0]), "r"((a)[1]), "r"((a)[2]), "r"((a)[3]), "r"(b0), "r"(b1))

__device__ __forceinline__ uint32_t pack_bf2(float x, float y) {
    __nv_bfloat16 hx = __float2bfloat16_rn(x), hy = __float2bfloat16_rn(y);
    return (uint32_t)__bfloat16_as_ushort(hx) | ((uint32_t)__bfloat16_as_ushort(hy) << 16);
}
__device__ __forceinline__ void split4(float4 v, uint2& hi, uint2& lo) {
    __nv_bfloat16 h0 = __float2bfloat16_rn(v.x), h1 = __float2bfloat16_rn(v.y);
    __nv_bfloat16 h2 = __float2bfloat16_rn(v.z), h3 = __float2bfloat16_rn(v.w);
    hi.x = (uint32_t)__bfloat16_as_ushort(h0) | ((uint32_t)__bfloat16_as_ushort(h1) << 16);
    hi.y = (uint32_t)__bfloat16_as_ushort(h2) | ((uint32_t)__bfloat16_as_ushort(h3) << 16);
    lo.x = pack_bf2(v.x - __bfloat162float(h0), v.y - __bfloat162float(h1));
    lo.y = pack_bf2(v.z - __bfloat162float(h2), v.w - __bfloat162float(h3));
}

// ---------------- CSR construction ----------------
__global__ void k_hist(const int* __restrict__ ei, int e) {
    int i = blockIdx.x * blockDim.x + threadIdx.x;
    if (i < e) atomicAdd(&g_deg[ei[e + i]], 1);
}
__global__ void k_scan(int n) {
    __shared__ int wsum[32];
    __shared__ int sbase;
    int lane = threadIdx.x & 31, wid = threadIdx.x >> 5;
    if (threadIdx.x == 0) sbase = 0;
    __syncthreads();
    for (int start = 0; start < n; start += 1024) {
        int i = start + threadIdx.x;
        int v = (i < n) ? g_deg[i] : 0;
        int s = v;
        #pragma unroll
        for (int o = 1; o < 32; o <<= 1) {
            int t = __shfl_up_sync(0xffffffffu, s, o);
            if (lane >= o) s += t;
        }
        if (lane == 31) wsum[wid] = s;
        __syncthreads();
        if (wid == 0) {
            int ws = wsum[lane];
            #pragma unroll
            for (int o = 1; o < 32; o <<= 1) {
                int t = __shfl_up_sync(0xffffffffu, ws, o);
                if (lane >= o) ws += t;
            }
            wsum[lane] = ws;
        }
        __syncthreads();
        int woff = (wid == 0) ? 0 : wsum[wid - 1];
        int excl = sbase + woff + s - v;
        if (i < n) { g_off[i] = excl; g_cur[i] = excl; }
        int total = wsum[31];
        __syncthreads();
        if (threadIdx.x == 0) sbase += total;
        __syncthreads();
    }
    if (threadIdx.x == 0) g_off[n] = sbase;
}
__global__ void k_scatter(const int* __restrict__ ei, int e) {
    int i = blockIdx.x * blockDim.x + threadIdx.x;
    if (i < e) {
        int dst = ei[e + i];
        int p = atomicAdd(&g_cur[dst], 1);
        g_src[p] = ei[i];
        g_dst[p] = dst;
    }
}

// ---------------- merged per-layer weight split ----------------
__global__ void k_wsplit4(const float* __restrict__ W0, const float* __restrict__ W1,
                          const float* __restrict__ W2, const float* __restrict__ W3) {
    int gid = blockIdx.x * blockDim.x + threadIdx.x;
    if (gid >= 4 * 768 * 128) return;
    int l = gid / (768 * 128), idx = gid % (768 * 128);
    const float* Wg = (l == 0) ? W0 : (l == 1) ? W1 : (l == 2) ? W2 : W3;
    int n = idx / 768, k = idx - n * 768;
    int h = k >> 7, kk = k & 127;
    float v = Wg[h * 16384 + n * 128 + kk];
    __nv_bfloat16 hi = __float2bfloat16_rn(v);
    g_Bh[l][idx] = hi;
    g_Bl[l][idx] = __float2bfloat16_rn(v - __bfloat162float(hi));
}

// ---------------- fused input layer + layer-1 t (warp per node) ----------------
__global__ void k_x0t(const float* __restrict__ pos, const float* __restrict__ nrm,
                      const float* __restrict__ w1, const float* __restrict__ b1,
                      const float* __restrict__ u, int n) {
    int gw = (blockIdx.x * blockDim.x + threadIdx.x) >> 5;
    int lane = threadIdx.x & 31;
    if (gw >= n) return;
    float p0 = pos[gw * 3 + 0], p1 = pos[gw * 3 + 1], p2 = pos[gw * 3 + 2];
    float n0 = nrm[gw * 3 + 0], n1 = nrm[gw * 3 + 1], n2 = nrm[gw * 3 + 2];
    float4 xv;
    float* xvp = (float*)&xv;
    #pragma unroll
    for (int j = 0; j < 4; j++) {
        int d = lane * 4 + j;
        const float* wr = w1 + d * 6;
        float a = b1[d];
        a = fmaf(p0, wr[0], a); a = fmaf(p1, wr[1], a); a = fmaf(p2, wr[2], a);
        a = fmaf(n0, wr[3], a); a = fmaf(n1, wr[4], a); a = fmaf(n2, wr[5], a);
        xvp[j] = fmaxf(a, 0.f);
    }
    *(float4*)(g_x0 + (size_t)gw * 128 + lane * 4) = xv;
    float a0, a1, a2, a3, a4, a5;
    {
        float4 w;
        w = *(const float4*)(u + 0 * 128 + lane * 4); a0 = xv.x*w.x + xv.y*w.y + xv.z*w.z + xv.w*w.w;
        w = *(const float4*)(u + 1 * 128 + lane * 4); a1 = xv.x*w.x + xv.y*w.y + xv.z*w.z + xv.w*w.w;
        w = *(const float4*)(u + 2 * 128 + lane * 4); a2 = xv.x*w.x + xv.y*w.y + xv.z*w.z + xv.w*w.w;
        w = *(const float4*)(u + 3 * 128 + lane * 4); a3 = xv.x*w.x + xv.y*w.y + xv.z*w.z + xv.w*w.w;
        w = *(const float4*)(u + 4 * 128 + lane * 4); a4 = xv.x*w.x + xv.y*w.y + xv.z*w.z + xv.w*w.w;
        w = *(const float4*)(u + 5 * 128 + lane * 4); a5 = xv.x*w.x + xv.y*w.y + xv.z*w.z + xv.w*w.w;
    }
    #pragma unroll
    for (int o = 16; o; o >>= 1) {
        a0 += __shfl_xor_sync(0xffffffffu, a0, o);
        a1 += __shfl_xor_sync(0xffffffffu, a1, o);
        a2 += __shfl_xor_sync(0xffffffffu, a2, o);
        a3 += __shfl_xor_sync(0xffffffffu, a3, o);
        a4 += __shfl_xor_sync(0xffffffffu, a4, o);
        a5 += __shfl_xor_sync(0xffffffffu, a5, o);
    }
    if (lane == 0) {
        float* tp = g_t + (size_t)gw * 8;
        tp[0] = a0; tp[1] = a1; tp[2] = a2; tp[3] = a3; tp[4] = a4; tp[5] = a5;
        tp[6] = 0.f; tp[7] = 0.f;
    }
}

// ---------------- fused edge softmax + aggregation (warp per dst node) ----------------
#define AGG_FMA(q0, q1, q2, q3, q4, q5, xv)                                                      \
    do {                                                                                         \
        a0.x = fmaf(q0, xv.x, a0.x); a0.y = fmaf(q0, xv.y, a0.y);                                \
        a0.z = fmaf(q0, xv.z, a0.z); a0.w = fmaf(q0, xv.w, a0.w);                                \
        a1.x = fmaf(q1, xv.x, a1.x); a1.y = fmaf(q1, xv.y, a1.y);                                \
        a1.z = fmaf(q1, xv.z, a1.z); a1.w = fmaf(q1, xv.w, a1.w);                                \
        a2.x = fmaf(q2, xv.x, a2.x); a2.y = fmaf(q2, xv.y, a2.y);                                \
        a2.z = fmaf(q2, xv.z, a2.z); a2.w = fmaf(q2, xv.w, a2.w);                                \
        a3.x = fmaf(q3, xv.x, a3.x); a3.y = fmaf(q3, xv.y, a3.y);                                \
        a3.z = fmaf(q3, xv.z, a3.z); a3.w = fmaf(q3, xv.w, a3.w);                                \
        a4.x = fmaf(q4, xv.x, a4.x); a4.y = fmaf(q4, xv.y, a4.y);                                \
        a4.z = fmaf(q4, xv.z, a4.z); a4.w = fmaf(q4, xv.w, a4.w);                                \
        a5.x = fmaf(q5, xv.x, a5.x); a5.y = fmaf(q5, xv.y, a5.y);                                \
        a5.z = fmaf(q5, xv.z, a5.z); a5.w = fmaf(q5, xv.w, a5.w);                                \
    } while (0)

__global__ void __launch_bounds__(256) k_agg(int sel, const float* __restrict__ cvec, int n) {
    __shared__ float sq[8][32][8];   // [warp][edge][head(6)+pad]
    __shared__ int   ssrc[8][32];

    int w = threadIdx.x >> 5;
    int gw = (blockIdx.x * blockDim.x + threadIdx.x) >> 5;
    int lane = threadIdx.x & 31;
    if (gw >= n) return;
    const float* x = sel ? g_x1 : g_x0;
    int beg = g_off[gw], end = g_off[gw + 1];
    float invdeg = 1.f / fmaxf((float)(end - beg), 1.f);

    float4 td0 = *(const float4*)&g_t[(size_t)gw * 8];
    float4 td1 = *(const float4*)&g_t[(size_t)gw * 8 + 4];
    float bb0 = cvec[0] - td0.x, bb1 = cvec[1] - td0.y, bb2 = cvec[2] - td0.z;
    float bb3 = cvec[3] - td0.w, bb4 = cvec[4] - td1.x, bb5 = cvec[5] - td1.y;

    float4 a0 = make_float4(0,0,0,0), a1 = a0, a2 = a0, a3 = a0, a4 = a0, a5 = a0;

    for (int base = beg; base < end; base += 32) {
        int cnt = min(32, end - base);
        if (lane < cnt) {
            int s = g_src[base + lane];
            ssrc[w][lane] = s;
            float4 ts0 = *(const float4*)&g_t[(size_t)s * 8];
            float4 ts1 = *(const float4*)&g_t[(size_t)s * 8 + 4];
            float s0 = ts0.x + bb0, s1 = ts0.y + bb1, s2 = ts0.z + bb2;
            float s3 = ts0.w + bb3, s4 = ts1.x + bb4, s5 = ts1.y + bb5;
            float mx = fmaxf(fmaxf(fmaxf(s0, s1), fmaxf(s2, s3)), fmaxf(s4, s5));
            float e0 = __expf(s0 - mx), e1 = __expf(s1 - mx), e2 = __expf(s2 - mx);
            float e3 = __expf(s3 - mx), e4 = __expf(s4 - mx), e5 = __expf(s5 - mx);
            float inv = __fdividef(invdeg, e0 + e1 + e2 + e3 + e4 + e5);
            *(float4*)&sq[w][lane][0] = make_float4(e0 * inv, e1 * inv, e2 * inv, e3 * inv);
            *(float2*)&sq[w][lane][4] = make_float2(e4 * inv, e5 * inv);
        }
        __syncwarp();
        int j = 0;
        for (; j + 4 <= cnt; j += 4) {
            int sA = ssrc[w][j], sB = ssrc[w][j + 1], sC = ssrc[w][j + 2], sD = ssrc[w][j + 3];
            float4 xvA = *(const float4*)(x + (size_t)sA * 128 + lane * 4);
            float4 xvB = *(const float4*)(x + (size_t)sB * 128 + lane * 4);
            float4 xvC = *(const float4*)(x + (size_t)sC * 128 + lane * 4);
            float4 xvD = *(const float4*)(x + (size_t)sD * 128 + lane * 4);
            float4 qa; float2 qb;
            qa = *(const float4*)&sq[w][j][0];     qb = *(const float2*)&sq[w][j][4];
            AGG_FMA(qa.x, qa.y, qa.z, qa.w, qb.x, qb.y, xvA);
            qa = *(const float4*)&sq[w][j + 1][0]; qb = *(const float2*)&sq[w][j + 1][4];
            AGG_FMA(qa.x, qa.y, qa.z, qa.w, qb.x, qb.y, xvB);
            qa = *(const float4*)&sq[w][j + 2][0]; qb = *(const float2*)&sq[w][j + 2][4];
            AGG_FMA(qa.x, qa.y, qa.z, qa.w, qb.x, qb.y, xvC);
            qa = *(const float4*)&sq[w][j + 3][0]; qb = *(const float2*)&sq[w][j + 3][4];
            AGG_FMA(qa.x, qa.y, qa.z, qa.w, qb.x, qb.y, xvD);
        }
        for (; j < cnt; j++) {
            int s = ssrc[w][j];
            float4 qa = *(const float4*)&sq[w][j][0];
            float2 qb = *(const float2*)&sq[w][j][4];
            float4 xv = *(const float4*)(x + (size_t)s * 128 + lane * 4);
            AGG_FMA(qa.x, qa.y, qa.z, qa.w, qb.x, qb.y, xv);
        }
        __syncwarp();
    }

    size_t obase = (size_t)gw * 768 + lane * 4;
    uint2 hi, lo;
    split4(a0, hi, lo); *(uint2*)(g_Ah + obase + 0 * 128) = hi; *(uint2*)(g_Al + obase + 0 * 128) = lo;
    split4(a1, hi, lo); *(uint2*)(g_Ah + obase + 1 * 128) = hi; *(uint2*)(g_Al + obase + 1 * 128) = lo;
    split4(a2, hi, lo); *(uint2*)(g_Ah + obase + 2 * 128) = hi; *(uint2*)(g_Al + obase + 2 * 128) = lo;
    split4(a3, hi, lo); *(uint2*)(g_Ah + obase + 3 * 128) = hi; *(uint2*)(g_Al + obase + 3 * 128) = lo;
    split4(a4, hi, lo); *(uint2*)(g_Ah + obase + 4 * 128) = hi; *(uint2*)(g_Al + obase + 4 * 128) = lo;
    split4(a5, hi, lo); *(uint2*)(g_Ah + obase + 5 * 128) = hi; *(uint2*)(g_Al + obase + 5 * 128) = lo;
}

// ---------------- GEMM + fused t (R12 config: 3-stage cp.async pipeline) ----------------
#define LDP 24

__global__ void __launch_bounds__(256, 2) k_gemm_mma(int l, const float* __restrict__ bias,
                                                     int outsel, const float* __restrict__ u_next,
                                                     int do_t) {
    __shared__ __nv_bfloat16 sm[3][2][2][128][LDP];
    __shared__ float su[128][6];     // u_next staged: su[col][h]
    __shared__ float st[2][128][6];  // per-warpN t partials

    const int tid = threadIdx.x;
    const int wid = tid >> 5, lane = tid & 31;
    const int warpM = wid & 3, warpN = wid >> 2;    // 4 x 2
    const int g = lane >> 2, tig = lane & 3;
    const int blockRow = blockIdx.x * 128;

    const int rowS = tid >> 1, halfS = tid & 1;
    const __nv_bfloat16* gBh = g_Bh[l];
    const __nv_bfloat16* gBl = g_Bl[l];

    float acc[2][8][4];
    #pragma unroll
    for (int mt = 0; mt < 2; mt++)
        #pragma unroll
        for (int nt = 0; nt < 8; nt++)
            #pragma unroll
            for (int j = 0; j < 4; j++) acc[mt][nt][j] = 0.f;

    const int lj = lane >> 3, lrr = lane & 7;
    const int lrow = (lj & 1) * 8 + lrr;
    const int lcol = (lj >> 1) * 8;

    auto stage_load = [&](int c, int st2) {
        int k0 = c * 16;
        cpa16(smem_u32(&sm[st2][0][0][rowS][halfS * 8]),
              g_Ah + (size_t)(blockRow + rowS) * 768 + k0 + halfS * 8);
        cpa16(smem_u32(&sm[st2][0][1][rowS][halfS * 8]),
              g_Al + (size_t)(blockRow + rowS) * 768 + k0 + halfS * 8);
        cpa16(smem_u32(&sm[st2][1][0][rowS][halfS * 8]),
              gBh + (size_t)rowS * 768 + k0 + halfS * 8);
        cpa16(smem_u32(&sm[st2][1][1][rowS][halfS * 8]),
              gBl + (size_t)rowS * 768 + k0 + halfS * 8);
        CP_COMMIT();
    };

    // 3-stage prologue: prefetch chunks 0 and 1
    stage_load(0, 0);
    stage_load(1, 1);

    if (do_t) {
        for (int i = tid; i < 768; i += 256) {
            int col = i / 6, h = i - col * 6;
            su[col][h] = u_next[h * 128 + col];
        }
    }

    int stg = 0;
    for (int c = 0; c < 48; c++) {
        if (c + 2 < 48) {
            stage_load(c + 2, (c + 2) % 3);
            asm volatile("cp.async.wait_group 2;");
        } else if (c + 1 < 48) {
            asm volatile("cp.async.wait_group 1;");
        } else {
            asm volatile("cp.async.wait_group 0;");
        }
        __syncthreads();

        uint32_t aF[2][2][4];
        #pragma unroll
        for (int s = 0; s < 2; s++)
            #pragma unroll
            for (int mt = 0; mt < 2; mt++)
                LDMX4(aF[s][mt], smem_u32(&sm[stg][0][s][warpM * 32 + mt * 16 + lrow][lcol]));
        #pragma unroll
        for (int ntp = 0; ntp < 4; ntp++) {
            uint32_t bh[4], bl[4];
            LDMX4(bh, smem_u32(&sm[stg][1][0][warpN * 64 + ntp * 16 + lrow][lcol]));
            LDMX4(bl, smem_u32(&sm[stg][1][1][warpN * 64 + ntp * 16 + lrow][lcol]));
            #pragma unroll
            for (int mt = 0; mt < 2; mt++) {
                float* dE = acc[mt][2 * ntp];
                float* dO = acc[mt][2 * ntp + 1];
                MMA_BF16(dE, aF[0][mt], bh[0], bh[2]);
                MMA_BF16(dE, aF[0][mt], bl[0], bl[2]);
                MMA_BF16(dE, aF[1][mt], bh[0], bh[2]);
                MMA_BF16(dO, aF[0][mt], bh[1], bh[3]);
                MMA_BF16(dO, aF[0][mt], bl[1], bl[3]);
                MMA_BF16(dO, aF[1][mt], bh[1], bh[3]);
            }
        }
        __syncthreads();
        stg = (stg + 1) % 3;
    }

    // ---- epilogue: bias + relu (+ t partials) ----
    float* C = outsel ? g_x1 : g_x0;
    float tp[2][2][6];
    #pragma unroll
    for (int mt = 0; mt < 2; mt++)
        #pragma unroll
        for (int rr = 0; rr < 2; rr++)
            #pragma unroll
            for (int h = 0; h < 6; h++) tp[mt][rr][h] = 0.f;

    #pragma unroll
    for (int nt = 0; nt < 8; nt++) {
        int col = warpN * 64 + nt * 8 + tig * 2;
        float b0 = bias[col], b1 = bias[col + 1];
        float u0[6], u1[6];
        if (do_t) {
            #pragma unroll
            for (int h = 0; h < 6; h++) { u0[h] = su[col][h]; u1[h] = su[col + 1][h]; }
        }
        #pragma unroll
        for (int mt = 0; mt < 2; mt++) {
            int r0 = blockRow + warpM * 32 + mt * 16 + g;
            float2 v0, v1;
            v0.x = fmaxf(acc[mt][nt][0] + b0, 0.f);
            v0.y = fmaxf(acc[mt][nt][1] + b1, 0.f);
            v1.x = fmaxf(acc[mt][nt][2] + b0, 0.f);
            v1.y = fmaxf(acc[mt][nt][3] + b1, 0.f);
            *(float2*)&C[(size_t)r0 * 128 + col] = v0;
            *(float2*)&C[(size_t)(r0 + 8) * 128 + col] = v1;
            if (do_t) {
                #pragma unroll
                for (int h = 0; h < 6; h++) {
                    tp[mt][0][h] = fmaf(v0.x, u0[h], fmaf(v0.y, u1[h], tp[mt][0][h]));
                    tp[mt][1][h] = fmaf(v1.x, u0[h], fmaf(v1.y, u1[h], tp[mt][1][h]));
                }
            }
        }
    }

    if (do_t) {
        #pragma unroll
        for (int mt = 0; mt < 2; mt++)
            #pragma unroll
            for (int rr = 0; rr < 2; rr++)
                #pragma unroll
                for (int h = 0; h < 6; h++) {
                    float v = tp[mt][rr][h];
                    v += __shfl_xor_sync(0xffffffffu, v, 1);
                    v += __shfl_xor_sync(0xffffffffu, v, 2);
                    tp[mt][rr][h] = v;
                }
        if (tig == 0) {
            #pragma unroll
            for (int mt = 0; mt < 2; mt++)
                #pragma unroll
                for (int rr = 0; rr < 2; rr++) {
                    int row = warpM * 32 + mt * 16 + rr * 8 + g;
                    #pragma unroll
                    for (int h = 0; h < 6; h++) st[warpN][row][h] = tp[mt][rr][h];
                }
        }
        __syncthreads();
        for (int i = tid; i < 768; i += 256) {
            int row = i / 6, h = i - row * 6;
            g_t[(size_t)(blockRow + row) * 8 + h] = st[0][row][h] + st[1][row][h];
        }
        for (int i = tid; i < 256; i += 256) {
            int row = i >> 1;
            g_t[(size_t)(blockRow + row) * 8 + 6 + (i & 1)] = 0.f;
        }
    }
}

// ---------------- output: out = x @ w2.T + b2 ----------------
__global__ void k_out(int sel, const float* __restrict__ w2, const float* __restrict__ b2,
                      float* __restrict__ out, int n) {
    int gw = (blockIdx.x * blockDim.x + threadIdx.x) >> 5;
    int lane = threadIdx.x & 31;
    if (gw >= n) return;
    const float* x = sel ? g_x1 : g_x0;
    float4 xv = *(const float4*)(x + (size_t)gw * 128 + lane * 4);
    float4 w;
    w = *(const float4*)(w2 + 0 * 128 + lane * 4);
    float a0 = xv.x * w.x + xv.y * w.y + xv.z * w.z + xv.w * w.w;
    w = *(const float4*)(w2 + 1 * 128 + lane * 4);
    float a1 = xv.x * w.x + xv.y * w.y + xv.z * w.z + xv.w * w.w;
    w = *(const float4*)(w2 + 2 * 128 + lane * 4);
    float a2 = xv.x * w.x + xv.y * w.y + xv.z * w.z + xv.w * w.w;
    #pragma unroll
    for (int o = 16; o; o >>= 1) {
        a0 += __shfl_xor_sync(0xffffffffu, a0, o);
        a1 += __shfl_xor_sync(0xffffffffu, a1, o);
        a2 += __shfl_xor_sync(0xffffffffu, a2, o);
    }
    if (lane == 0) {
        out[(size_t)gw * 3 + 0] = a0 + b2[0];
        out[(size_t)gw * 3 + 1] = a1 + b2[1];
        out[(size_t)gw * 3 + 2] = a2 + b2[2];
    }
}

// ---------------- launch ----------------
extern "C" void kernel_launch(void* const* d_in, const int* in_sizes, int n_in,
                              void* d_out, int out_size) {
    const float* pos = (const float*)d_in[0];
    const float* nrm = (const float*)d_in[1];
    const int*   ei  = (const int*)d_in[2];
    const float* w1  = (const float*)d_in[3];
    const float* b1  = (const float*)d_in[4];
    const float* w2  = (const float*)d_in[5];
    const float* b2  = (const float*)d_in[6];
    const float* Wg[4] = {(const float*)d_in[7],  (const float*)d_in[11],
                          (const float*)d_in[15], (const float*)d_in[19]};
    const float* u[4]  = {(const float*)d_in[8],  (const float*)d_in[12],
                          (const float*)d_in[16], (const float*)d_in[20]};
    const float* c[4]  = {(const float*)d_in[9],  (const float*)d_in[13],
                          (const float*)d_in[17], (const float*)d_in[21]};
    const float* bg[4] = {(const float*)d_in[10], (const float*)d_in[14],
                          (const float*)d_in[18], (const float*)d_in[22]};

    int n = in_sizes[0] / 3;   // 50000
    int e = in_sizes[2] / 2;   // 800000

    // CSR build (deg zeroed by capturable async memset)
    void* degp = nullptr;
    cudaGetSymbolAddress(&degp, g_deg);
    cudaMemsetAsync(degp, 0, (size_t)n * sizeof(int));
    k_hist<<<(e + 255) / 256, 256>>>(ei, e);
    k_scan<<<1, 1024>>>(n);
    k_scatter<<<(e + 255) / 256, 256>>>(ei, e);

    // merged weight hi/lo split (all 4 layers)
    k_wsplit4<<<(4 * 768 * 128 + 255) / 256, 256>>>(Wg[0], Wg[1], Wg[2], Wg[3]);

    // fused input layer + layer-1 t
    int warp_blocks = (n * 32 + 255) / 256;
    k_x0t<<<warp_blocks, 256>>>(pos, nrm, w1, b1, u[0], n);

    // 4 feast layers (ping-pong x between g_x0 / g_x1)
    int sel = 0;
    int gemm_blocks = (n + 127) / 128;     // 391
    for (int l = 0; l < 4; l++) {
        k_agg<<<warp_blocks, 256>>>(sel, c[l], n);
        int do_t = (l < 3);
        k_gemm_mma<<<gemm_blocks, 256>>>(l, bg[l], 1 - sel, do_t ? u[l + 1] : u[0], do_t);
        sel = 1 - sel;
    }

    // output projection
    k_out<<<warp_blocks, 256>>>(sel, w2, b2, (float*)d_out, n);
}

// round 15
// speedup vs baseline: 1.0174x; 1.0174x over previous
#include <cuda_runtime.h>
#include <cuda_bf16.h>
#include <math.h>
#include <stdint.h>

// ---------------- static scratch (no allocations allowed) ----------------
#define MAXN   50048            // padded (391*128)
#define MAXE   800000

__device__ float g_x0[MAXN * 128];
__device__ float g_x1[MAXN * 128];
__device__ __nv_bfloat16 g_Ah[(size_t)MAXN * 768];   // agg hi split (bf16)
__device__ __nv_bfloat16 g_Al[(size_t)MAXN * 768];   // agg lo split
__device__ float g_t[MAXN * 8];          // [N,6] padded to 8
__device__ __nv_bfloat16 g_Bh[4][768 * 128];  // B split hi: [l][n*768+k]
__device__ __nv_bfloat16 g_Bl[4][768 * 128];  // B split lo
__device__ int   g_deg[MAXN];
__device__ int   g_off[MAXN + 1];
__device__ int   g_cur[MAXN];
__device__ int   g_src[MAXE];
__device__ int   g_dst[MAXE];

// ---------------- helpers ----------------
__device__ __forceinline__ uint32_t smem_u32(const void* p) {
    uint32_t a;
    asm("{ .reg .u64 t; cvta.to.shared.u64 t, %1; cvt.u32.u64 %0, t; }" : "=r"(a) : "l"(p));
    return a;
}
__device__ __forceinline__ void cpa16(uint32_t dst, const void* src) {
    asm volatile("cp.async.cg.shared.global [%0], [%1], 16;" :: "r"(dst), "l"(src));
}
#define CP_COMMIT() asm volatile("cp.async.commit_group;")
#define LDMX4(r, addr)                                                          \
    asm volatile("ldmatrix.sync.aligned.m8n8.x4.shared.b16 {%0,%1,%2,%3}, [%4];"\
        : "=r"((r)[0]), "=r"((r)[1]), "=r"((r)[2]), "=r"((r)[3]) : "r"(addr))
#define MMA_BF16(d, a, b0, b1)                                                  \
    asm volatile("mma.sync.aligned.m16n8k16.row.col.f32.bf16.bf16.f32 "         \
        "{%0,%1,%2,%3}, {%4,%5,%6,%7}, {%8,%9}, {%0,%1,%2,%3};"                 \
        : "+f"((d)[0]), "+f"((d)[1]), "+f"((d)[2]), "+f"((d)[3])                \
        : "r"((a)[0]), "r"((a)[1]), "r"((a)[2]), "r"((a)[3]), "r"(b0), "r"(b1))

__device__ __forceinline__ uint32_t pack_bf2(float x, float y) {
    __nv_bfloat16 hx = __float2bfloat16_rn(x), hy = __float2bfloat16_rn(y);
    return (uint32_t)__bfloat16_as_ushort(hx) | ((uint32_t)__bfloat16_as_ushort(hy) << 16);
}
__device__ __forceinline__ void split4(float4 v, uint2& hi, uint2& lo) {
    __nv_bfloat16 h0 = __float2bfloat16_rn(v.x), h1 = __float2bfloat16_rn(v.y);
    __nv_bfloat16 h2 = __float2bfloat16_rn(v.z), h3 = __float2bfloat16_rn(v.w);
    hi.x = (uint32_t)__bfloat16_as_ushort(h0) | ((uint32_t)__bfloat16_as_ushort(h1) << 16);
    hi.y = (uint32_t)__bfloat16_as_ushort(h2) | ((uint32_t)__bfloat16_as_ushort(h3) << 16);
    lo.x = pack_bf2(v.x - __bfloat162float(h0), v.y - __bfloat162float(h1));
    lo.y = pack_bf2(v.z - __bfloat162float(h2), v.w - __bfloat162float(h3));
}

// ---------------- CSR construction ----------------
__global__ void k_hist(const int* __restrict__ ei, int e) {
    int i = blockIdx.x * blockDim.x + threadIdx.x;
    if (i < e) atomicAdd(&g_deg[__ldg(ei + e + i)], 1);
}
__global__ void k_scan(int n) {
    __shared__ int wsum[32];
    __shared__ int sbase;
    int lane = threadIdx.x & 31, wid = threadIdx.x >> 5;
    if (threadIdx.x == 0) sbase = 0;
    __syncthreads();
    for (int start = 0; start < n; start += 1024) {
        int i = start + threadIdx.x;
        int v = (i < n) ? g_deg[i] : 0;
        int s = v;
        #pragma unroll
        for (int o = 1; o < 32; o <<= 1) {
            int t = __shfl_up_sync(0xffffffffu, s, o);
            if (lane >= o) s += t;
        }
        if (lane == 31) wsum[wid] = s;
        __syncthreads();
        if (wid == 0) {
            int ws = wsum[lane];
            #pragma unroll
            for (int o = 1; o < 32; o <<= 1) {
                int t = __shfl_up_sync(0xffffffffu, ws, o);
                if (lane >= o) ws += t;
            }
            wsum[lane] = ws;
        }
        __syncthreads();
        int woff = (wid == 0) ? 0 : wsum[wid - 1];
        int excl = sbase + woff + s - v;
        if (i < n) { g_off[i] = excl; g_cur[i] = excl; }
        int total = wsum[31];
        __syncthreads();
        if (threadIdx.x == 0) sbase += total;
        __syncthreads();
    }
    if (threadIdx.x == 0) g_off[n] = sbase;
}
__global__ void k_scatter(const int* __restrict__ ei, int e) {
    int i = blockIdx.x * blockDim.x + threadIdx.x;
    if (i < e) {
        int dst = __ldg(ei + e + i);
        int p = atomicAdd(&g_cur[dst], 1);
        g_src[p] = __ldg(ei + i);
        g_dst[p] = dst;
    }
}

// ---------------- merged per-layer weight split ----------------
__global__ void k_wsplit4(const float* __restrict__ W0, const float* __restrict__ W1,
                          const float* __restrict__ W2, const float* __restrict__ W3) {
    int gid = blockIdx.x * blockDim.x + threadIdx.x;
    if (gid >= 4 * 768 * 128) return;
    int l = gid / (768 * 128), idx = gid % (768 * 128);
    const float* Wg = (l == 0) ? W0 : (l == 1) ? W1 : (l == 2) ? W2 : W3;
    int n = idx / 768, k = idx - n * 768;
    int h = k >> 7, kk = k & 127;
    float v = Wg[h * 16384 + n * 128 + kk];
    __nv_bfloat16 hi = __float2bfloat16_rn(v);
    g_Bh[l][idx] = hi;
    g_Bl[l][idx] = __float2bfloat16_rn(v - __bfloat162float(hi));
}

// ---------------- input layer ----------------
__global__ void k_x0(const float* __restrict__ pos, const float* __restrict__ nrm,
                     const float* __restrict__ w1, const float* __restrict__ b1, int n) {
    int gid = blockIdx.x * blockDim.x + threadIdx.x;
    if (gid >= n * 128) return;
    int i = gid >> 7, d = gid & 127;
    const float* wr = w1 + d * 6;
    float a = b1[d];
    a = fmaf(pos[i * 3 + 0], wr[0], a);
    a = fmaf(pos[i * 3 + 1], wr[1], a);
    a = fmaf(pos[i * 3 + 2], wr[2], a);
    a = fmaf(nrm[i * 3 + 0], wr[3], a);
    a = fmaf(nrm[i * 3 + 1], wr[4], a);
    a = fmaf(nrm[i * 3 + 2], wr[5], a);
    g_x0[(size_t)i * 128 + d] = fmaxf(a, 0.f);
}

// ---------------- t = x @ u.T (standalone; layer 1 only) ----------------
__global__ void k_t(int sel, const float* __restrict__ u, int n) {
    int gw = (blockIdx.x * blockDim.x + threadIdx.x) >> 5;
    int lane = threadIdx.x & 31;
    if (gw >= n) return;
    const float* x = sel ? g_x1 : g_x0;
    float4 xv = *(const float4*)(x + (size_t)gw * 128 + lane * 4);
    float a0, a1, a2, a3, a4, a5;
    {
        float4 w;
        w = *(const float4*)(u + 0 * 128 + lane * 4); a0 = xv.x*w.x + xv.y*w.y + xv.z*w.z + xv.w*w.w;
        w = *(const float4*)(u + 1 * 128 + lane * 4); a1 = xv.x*w.x + xv.y*w.y + xv.z*w.z + xv.w*w.w;
        w = *(const float4*)(u + 2 * 128 + lane * 4); a2 = xv.x*w.x + xv.y*w.y + xv.z*w.z + xv.w*w.w;
        w = *(const float4*)(u + 3 * 128 + lane * 4); a3 = xv.x*w.x + xv.y*w.y + xv.z*w.z + xv.w*w.w;
        w = *(const float4*)(u + 4 * 128 + lane * 4); a4 = xv.x*w.x + xv.y*w.y + xv.z*w.z + xv.w*w.w;
        w = *(const float4*)(u + 5 * 128 + lane * 4); a5 = xv.x*w.x + xv.y*w.y + xv.z*w.z + xv.w*w.w;
    }
    #pragma unroll
    for (int o = 16; o; o >>= 1) {
        a0 += __shfl_xor_sync(0xffffffffu, a0, o);
        a1 += __shfl_xor_sync(0xffffffffu, a1, o);
        a2 += __shfl_xor_sync(0xffffffffu, a2, o);
        a3 += __shfl_xor_sync(0xffffffffu, a3, o);
        a4 += __shfl_xor_sync(0xffffffffu, a4, o);
        a5 += __shfl_xor_sync(0xffffffffu, a5, o);
    }
    if (lane == 0) {
        float* tp = g_t + (size_t)gw * 8;
        tp[0] = a0; tp[1] = a1; tp[2] = a2; tp[3] = a3; tp[4] = a4; tp[5] = a5;
        tp[6] = 0.f; tp[7] = 0.f;
    }
}

// ---------------- fused edge softmax + aggregation (warp per dst node) ----------------
#define AGG_FMA(q0, q1, q2, q3, q4, q5, xv)                                                      \
    do {                                                                                         \
        a0.x = fmaf(q0, xv.x, a0.x); a0.y = fmaf(q0, xv.y, a0.y);                                \
        a0.z = fmaf(q0, xv.z, a0.z); a0.w = fmaf(q0, xv.w, a0.w);                                \
        a1.x = fmaf(q1, xv.x, a1.x); a1.y = fmaf(q1, xv.y, a1.y);                                \
        a1.z = fmaf(q1, xv.z, a1.z); a1.w = fmaf(q1, xv.w, a1.w);                                \
        a2.x = fmaf(q2, xv.x, a2.x); a2.y = fmaf(q2, xv.y, a2.y);                                \
        a2.z = fmaf(q2, xv.z, a2.z); a2.w = fmaf(q2, xv.w, a2.w);                                \
        a3.x = fmaf(q3, xv.x, a3.x); a3.y = fmaf(q3, xv.y, a3.y);                                \
        a3.z = fmaf(q3, xv.z, a3.z); a3.w = fmaf(q3, xv.w, a3.w);                                \
        a4.x = fmaf(q4, xv.x, a4.x); a4.y = fmaf(q4, xv.y, a4.y);                                \
        a4.z = fmaf(q4, xv.z, a4.z); a4.w = fmaf(q4, xv.w, a4.w);                                \
        a5.x = fmaf(q5, xv.x, a5.x); a5.y = fmaf(q5, xv.y, a5.y);                                \
        a5.z = fmaf(q5, xv.z, a5.z); a5.w = fmaf(q5, xv.w, a5.w);                                \
    } while (0)

__global__ void __launch_bounds__(256) k_agg(int sel, const float* __restrict__ cvec, int n) {
    __shared__ float sq[8][32][8];   // [warp][edge][head(6)+pad]
    __shared__ int   ssrc[8][32];

    int w = threadIdx.x >> 5;
    int gw = (blockIdx.x * blockDim.x + threadIdx.x) >> 5;
    int lane = threadIdx.x & 31;
    if (gw >= n) return;
    const float* x = sel ? g_x1 : g_x0;
    int beg = g_off[gw], end = g_off[gw + 1];
    float invdeg = 1.f / fmaxf((float)(end - beg), 1.f);

    float4 td0 = *(const float4*)&g_t[(size_t)gw * 8];
    float4 td1 = *(const float4*)&g_t[(size_t)gw * 8 + 4];
    float bb0 = cvec[0] - td0.x, bb1 = cvec[1] - td0.y, bb2 = cvec[2] - td0.z;
    float bb3 = cvec[3] - td0.w, bb4 = cvec[4] - td1.x, bb5 = cvec[5] - td1.y;

    float4 a0 = make_float4(0,0,0,0), a1 = a0, a2 = a0, a3 = a0, a4 = a0, a5 = a0;

    for (int base = beg; base < end; base += 32) {
        int cnt = min(32, end - base);
        if (lane < cnt) {
            int s = g_src[base + lane];
            ssrc[w][lane] = s;
            float4 ts0 = *(const float4*)&g_t[(size_t)s * 8];
            float4 ts1 = *(const float4*)&g_t[(size_t)s * 8 + 4];
            float s0 = ts0.x + bb0, s1 = ts0.y + bb1, s2 = ts0.z + bb2;
            float s3 = ts0.w + bb3, s4 = ts1.x + bb4, s5 = ts1.y + bb5;
            float mx = fmaxf(fmaxf(fmaxf(s0, s1), fmaxf(s2, s3)), fmaxf(s4, s5));
            float e0 = __expf(s0 - mx), e1 = __expf(s1 - mx), e2 = __expf(s2 - mx);
            float e3 = __expf(s3 - mx), e4 = __expf(s4 - mx), e5 = __expf(s5 - mx);
            float inv = __fdividef(invdeg, e0 + e1 + e2 + e3 + e4 + e5);
            *(float4*)&sq[w][lane][0] = make_float4(e0 * inv, e1 * inv, e2 * inv, e3 * inv);
            *(float2*)&sq[w][lane][4] = make_float2(e4 * inv, e5 * inv);
        }
        __syncwarp();
        int j = 0;
        for (; j + 4 <= cnt; j += 4) {
            int sA = ssrc[w][j], sB = ssrc[w][j + 1], sC = ssrc[w][j + 2], sD = ssrc[w][j + 3];
            float4 xvA = *(const float4*)(x + (size_t)sA * 128 + lane * 4);
            float4 xvB = *(const float4*)(x + (size_t)sB * 128 + lane * 4);
            float4 xvC = *(const float4*)(x + (size_t)sC * 128 + lane * 4);
            float4 xvD = *(const float4*)(x + (size_t)sD * 128 + lane * 4);
            float4 qa; float2 qb;
            qa = *(const float4*)&sq[w][j][0];     qb = *(const float2*)&sq[w][j][4];
            AGG_FMA(qa.x, qa.y, qa.z, qa.w, qb.x, qb.y, xvA);
            qa = *(const float4*)&sq[w][j + 1][0]; qb = *(const float2*)&sq[w][j + 1][4];
            AGG_FMA(qa.x, qa.y, qa.z, qa.w, qb.x, qb.y, xvB);
            qa = *(const float4*)&sq[w][j + 2][0]; qb = *(const float2*)&sq[w][j + 2][4];
            AGG_FMA(qa.x, qa.y, qa.z, qa.w, qb.x, qb.y, xvC);
            qa = *(const float4*)&sq[w][j + 3][0]; qb = *(const float2*)&sq[w][j + 3][4];
            AGG_FMA(qa.x, qa.y, qa.z, qa.w, qb.x, qb.y, xvD);
        }
        for (; j < cnt; j++) {
            int s = ssrc[w][j];
            float4 qa = *(const float4*)&sq[w][j][0];
            float2 qb = *(const float2*)&sq[w][j][4];
            float4 xv = *(const float4*)(x + (size_t)s * 128 + lane * 4);
            AGG_FMA(qa.x, qa.y, qa.z, qa.w, qb.x, qb.y, xv);
        }
        __syncwarp();
    }

    size_t obase = (size_t)gw * 768 + lane * 4;
    uint2 hi, lo;
    split4(a0, hi, lo); *(uint2*)(g_Ah + obase + 0 * 128) = hi; *(uint2*)(g_Al + obase + 0 * 128) = lo;
    split4(a1, hi, lo); *(uint2*)(g_Ah + obase + 1 * 128) = hi; *(uint2*)(g_Al + obase + 1 * 128) = lo;
    split4(a2, hi, lo); *(uint2*)(g_Ah + obase + 2 * 128) = hi; *(uint2*)(g_Al + obase + 2 * 128) = lo;
    split4(a3, hi, lo); *(uint2*)(g_Ah + obase + 3 * 128) = hi; *(uint2*)(g_Al + obase + 3 * 128) = lo;
    split4(a4, hi, lo); *(uint2*)(g_Ah + obase + 4 * 128) = hi; *(uint2*)(g_Al + obase + 4 * 128) = lo;
    split4(a5, hi, lo); *(uint2*)(g_Ah + obase + 5 * 128) = hi; *(uint2*)(g_Al + obase + 5 * 128) = lo;
}

// ---------------- GEMM + fused t (R12 config: 3-stage cp.async pipeline) ----------------
#define LDP 24

__global__ void __launch_bounds__(256, 2) k_gemm_mma(int l, const float* __restrict__ bias,
                                                     int outsel, const float* __restrict__ u_next,
                                                     int do_t) {
    __shared__ __nv_bfloat16 sm[3][2][2][128][LDP];
    __shared__ float su[128][6];     // u_next staged: su[col][h]
    __shared__ float st[2][128][6];  // per-warpN t partials

    const int tid = threadIdx.x;
    const int wid = tid >> 5, lane = tid & 31;
    const int warpM = wid & 3, warpN = wid >> 2;    // 4 x 2
    const int g = lane >> 2, tig = lane & 3;
    const int blockRow = blockIdx.x * 128;

    const int rowS = tid >> 1, halfS = tid & 1;
    const __nv_bfloat16* gBh = g_Bh[l];
    const __nv_bfloat16* gBl = g_Bl[l];

    float acc[2][8][4];
    #pragma unroll
    for (int mt = 0; mt < 2; mt++)
        #pragma unroll
        for (int nt = 0; nt < 8; nt++)
            #pragma unroll
            for (int j = 0; j < 4; j++) acc[mt][nt][j] = 0.f;

    const int lj = lane >> 3, lrr = lane & 7;
    const int lrow = (lj & 1) * 8 + lrr;
    const int lcol = (lj >> 1) * 8;

    auto stage_load = [&](int c, int st2) {
        int k0 = c * 16;
        cpa16(smem_u32(&sm[st2][0][0][rowS][halfS * 8]),
              g_Ah + (size_t)(blockRow + rowS) * 768 + k0 + halfS * 8);
        cpa16(smem_u32(&sm[st2][0][1][rowS][halfS * 8]),
              g_Al + (size_t)(blockRow + rowS) * 768 + k0 + halfS * 8);
        cpa16(smem_u32(&sm[st2][1][0][rowS][halfS * 8]),
              gBh + (size_t)rowS * 768 + k0 + halfS * 8);
        cpa16(smem_u32(&sm[st2][1][1][rowS][halfS * 8]),
              gBl + (size_t)rowS * 768 + k0 + halfS * 8);
        CP_COMMIT();
    };

    // 3-stage prologue: prefetch chunks 0 and 1
    stage_load(0, 0);
    stage_load(1, 1);

    if (do_t) {
        for (int i = tid; i < 768; i += 256) {
            int col = i / 6, h = i - col * 6;
            su[col][h] = u_next[h * 128 + col];
        }
    }

    int stg = 0;
    for (int c = 0; c < 48; c++) {
        if (c + 2 < 48) {
            stage_load(c + 2, (c + 2) % 3);
            asm volatile("cp.async.wait_group 2;");
        } else if (c + 1 < 48) {
            asm volatile("cp.async.wait_group 1;");
        } else {
            asm volatile("cp.async.wait_group 0;");
        }
        __syncthreads();

        uint32_t aF[2][2][4];
        #pragma unroll
        for (int s = 0; s < 2; s++)
            #pragma unroll
            for (int mt = 0; mt < 2; mt++)
                LDMX4(aF[s][mt], smem_u32(&sm[stg][0][s][warpM * 32 + mt * 16 + lrow][lcol]));
        #pragma unroll
        for (int ntp = 0; ntp < 4; ntp++) {
            uint32_t bh[4], bl[4];
            LDMX4(bh, smem_u32(&sm[stg][1][0][warpN * 64 + ntp * 16 + lrow][lcol]));
            LDMX4(bl, smem_u32(&sm[stg][1][1][warpN * 64 + ntp * 16 + lrow][lcol]));
            #pragma unroll
            for (int mt = 0; mt < 2; mt++) {
                float* dE = acc[mt][2 * ntp];
                float* dO = acc[mt][2 * ntp + 1];
                MMA_BF16(dE, aF[0][mt], bh[0], bh[2]);
                MMA_BF16(dE, aF[0][mt], bl[0], bl[2]);
                MMA_BF16(dE, aF[1][mt], bh[0], bh[2]);
                MMA_BF16(dO, aF[0][mt], bh[1], bh[3]);
                MMA_BF16(dO, aF[0][mt], bl[1], bl[3]);
                MMA_BF16(dO, aF[1][mt], bh[1], bh[3]);
            }
        }
        __syncthreads();
        stg = (stg + 1) % 3;
    }

    // ---- epilogue: bias + relu (+ t partials) ----
    float* C = outsel ? g_x1 : g_x0;
    float tp[2][2][6];
    #pragma unroll
    for (int mt = 0; mt < 2; mt++)
        #pragma unroll
        for (int rr = 0; rr < 2; rr++)
            #pragma unroll
            for (int h = 0; h < 6; h++) tp[mt][rr][h] = 0.f;

    #pragma unroll
    for (int nt = 0; nt < 8; nt++) {
        int col = warpN * 64 + nt * 8 + tig * 2;
        float b0 = bias[col], b1 = bias[col + 1];
        float u0[6], u1[6];
        if (do_t) {
            #pragma unroll
            for (int h = 0; h < 6; h++) { u0[h] = su[col][h]; u1[h] = su[col + 1][h]; }
        }
        #pragma unroll
        for (int mt = 0; mt < 2; mt++) {
            int r0 = blockRow + warpM * 32 + mt * 16 + g;
            float2 v0, v1;
            v0.x = fmaxf(acc[mt][nt][0] + b0, 0.f);
            v0.y = fmaxf(acc[mt][nt][1] + b1, 0.f);
            v1.x = fmaxf(acc[mt][nt][2] + b0, 0.f);
            v1.y = fmaxf(acc[mt][nt][3] + b1, 0.f);
            *(float2*)&C[(size_t)r0 * 128 + col] = v0;
            *(float2*)&C[(size_t)(r0 + 8) * 128 + col] = v1;
            if (do_t) {
                #pragma unroll
                for (int h = 0; h < 6; h++) {
                    tp[mt][0][h] = fmaf(v0.x, u0[h], fmaf(v0.y, u1[h], tp[mt][0][h]));
                    tp[mt][1][h] = fmaf(v1.x, u0[h], fmaf(v1.y, u1[h], tp[mt][1][h]));
                }
            }
        }
    }

    if (do_t) {
        #pragma unroll
        for (int mt = 0; mt < 2; mt++)
            #pragma unroll
            for (int rr = 0; rr < 2; rr++)
                #pragma unroll
                for (int h = 0; h < 6; h++) {
                    float v = tp[mt][rr][h];
                    v += __shfl_xor_sync(0xffffffffu, v, 1);
                    v += __shfl_xor_sync(0xffffffffu, v, 2);
                    tp[mt][rr][h] = v;
                }
        if (tig == 0) {
            #pragma unroll
            for (int mt = 0; mt < 2; mt++)
                #pragma unroll
                for (int rr = 0; rr < 2; rr++) {
                    int row = warpM * 32 + mt * 16 + rr * 8 + g;
                    #pragma unroll
                    for (int h = 0; h < 6; h++) st[warpN][row][h] = tp[mt][rr][h];
                }
        }
        __syncthreads();
        for (int i = tid; i < 768; i += 256) {
            int row = i / 6, h = i - row * 6;
            g_t[(size_t)(blockRow + row) * 8 + h] = st[0][row][h] + st[1][row][h];
        }
        for (int i = tid; i < 256; i += 256) {
            int row = i >> 1;
            g_t[(size_t)(blockRow + row) * 8 + 6 + (i & 1)] = 0.f;
        }
    }
}

// ---------------- output: out = x @ w2.T + b2 ----------------
__global__ void k_out(int sel, const float* __restrict__ w2, const float* __restrict__ b2,
                      float* __restrict__ out, int n) {
    int gw = (blockIdx.x * blockDim.x + threadIdx.x) >> 5;
    int lane = threadIdx.x & 31;
    if (gw >= n) return;
    const float* x = sel ? g_x1 : g_x0;
    float4 xv = *(const float4*)(x + (size_t)gw * 128 + lane * 4);
    float4 w;
    w = *(const float4*)(w2 + 0 * 128 + lane * 4);
    float a0 = xv.x * w.x + xv.y * w.y + xv.z * w.z + xv.w * w.w;
    w = *(const float4*)(w2 + 1 * 128 + lane * 4);
    float a1 = xv.x * w.x + xv.y * w.y + xv.z * w.z + xv.w * w.w;
    w = *(const float4*)(w2 + 2 * 128 + lane * 4);
    float a2 = xv.x * w.x + xv.y * w.y + xv.z * w.z + xv.w * w.w;
    #pragma unroll
    for (int o = 16; o; o >>= 1) {
        a0 += __shfl_xor_sync(0xffffffffu, a0, o);
        a1 += __shfl_xor_sync(0xffffffffu, a1, o);
        a2 += __shfl_xor_sync(0xffffffffu, a2, o);
    }
    if (lane == 0) {
        out[(size_t)gw * 3 + 0] = a0 + b2[0];
        out[(size_t)gw * 3 + 1] = a1 + b2[1];
        out[(size_t)gw * 3 + 2] = a2 + b2[2];
    }
}

// ---------------- launch ----------------
extern "C" void kernel_launch(void* const* d_in, const int* in_sizes, int n_in,
                              void* d_out, int out_size) {
    const float* pos = (const float*)d_in[0];
    const float* nrm = (const float*)d_in[1];
    const int*   ei  = (const int*)d_in[2];
    const float* w1  = (const float*)d_in[3];
    const float* b1  = (const float*)d_in[4];
    const float* w2  = (const float*)d_in[5];
    const float* b2  = (const float*)d_in[6];
    const float* Wg[4] = {(const float*)d_in[7],  (const float*)d_in[11],
                          (const float*)d_in[15], (const float*)d_in[19]};
    const float* u[4]  = {(const float*)d_in[8],  (const float*)d_in[12],
                          (const float*)d_in[16], (const float*)d_in[20]};
    const float* c[4]  = {(const float*)d_in[9],  (const float*)d_in[13],
                          (const float*)d_in[17], (const float*)d_in[21]};
    const float* bg[4] = {(const float*)d_in[10], (const float*)d_in[14],
                          (const float*)d_in[18], (const float*)d_in[22]};

    int n = in_sizes[0] / 3;   // 50000
    int e = in_sizes[2] / 2;   // 800000

    // CSR build (deg zeroed by capturable async memset)
    void* degp = nullptr;
    cudaGetSymbolAddress(&degp, g_deg);
    cudaMemsetAsync(degp, 0, (size_t)n * sizeof(int));
    k_hist<<<(e + 255) / 256, 256>>>(ei, e);
    k_scan<<<1, 1024>>>(n);
    k_scatter<<<(e + 255) / 256, 256>>>(ei, e);

    // merged weight hi/lo split (all 4 layers)
    k_wsplit4<<<(4 * 768 * 128 + 255) / 256, 256>>>(Wg[0], Wg[1], Wg[2], Wg[3]);

    // input layer
    k_x0<<<(n * 128 + 255) / 256, 256>>>(pos, nrm, w1, b1, n);

    // 4 feast layers (ping-pong x between g_x0 / g_x1)
    int sel = 0;
    int warp_blocks = (n * 32 + 255) / 256;
    int gemm_blocks = (n + 127) / 128;     // 391
    k_t<<<warp_blocks, 256>>>(0, u[0], n);
    for (int l = 0; l < 4; l++) {
        k_agg<<<warp_blocks, 256>>>(sel, c[l], n);
        int do_t = (l < 3);
        k_gemm_mma<<<gemm_blocks, 256>>>(l, bg[l], 1 - sel, do_t ? u[l + 1] : u[0], do_t);
        sel = 1 - sel;
    }

    // output projection
    k_out<<<warp_blocks, 256>>>(sel, w2, b2, (float*)d_out, n);
}

// round 16
// speedup vs baseline: 1.0224x; 1.0050x over previous
#include <cuda_runtime.h>
#include <cuda_bf16.h>
#include <math.h>
#include <stdint.h>

// ---------------- static scratch (no allocations allowed) ----------------
#define MAXN   50048            // padded (391*128)
#define MAXE   800000

__device__ float g_x0[MAXN * 128];
__device__ float g_x1[MAXN * 128];
__device__ __nv_bfloat16 g_Ah[(size_t)MAXN * 768];   // agg hi split (bf16)
__device__ __nv_bfloat16 g_Al[(size_t)MAXN * 768];   // agg lo split
__device__ float g_t[MAXN * 8];          // [N,6] padded to 8
__device__ __nv_bfloat16 g_Bh[4][768 * 128];  // B split hi: [l][n*768+k]
__device__ __nv_bfloat16 g_Bl[4][768 * 128];  // B split lo
__device__ int   g_deg[MAXN];
__device__ int   g_off[MAXN + 1];
__device__ int   g_cur[MAXN];
__device__ int   g_src[MAXE];

// ---------------- helpers ----------------
__device__ __forceinline__ uint32_t smem_u32(const void* p) {
    uint32_t a;
    asm("{ .reg .u64 t; cvta.to.shared.u64 t, %1; cvt.u32.u64 %0, t; }" : "=r"(a) : "l"(p));
    return a;
}
__device__ __forceinline__ void cpa16(uint32_t dst, const void* src) {
    asm volatile("cp.async.cg.shared.global [%0], [%1], 16;" :: "r"(dst), "l"(src));
}
#define CP_COMMIT() asm volatile("cp.async.commit_group;")
#define LDMX4(r, addr)                                                          \
    asm volatile("ldmatrix.sync.aligned.m8n8.x4.shared.b16 {%0,%1,%2,%3}, [%4];"\
        : "=r"((r)[0]), "=r"((r)[1]), "=r"((r)[2]), "=r"((r)[3]) : "r"(addr))
#define MMA_BF16(d, a, b0, b1)                                                  \
    asm volatile("mma.sync.aligned.m16n8k16.row.col.f32.bf16.bf16.f32 "         \
        "{%0,%1,%2,%3}, {%4,%5,%6,%7}, {%8,%9}, {%0,%1,%2,%3};"                 \
        : "+f"((d)[0]), "+f"((d)[1]), "+f"((d)[2]), "+f"((d)[3])                \
        : "r"((a)[0]), "r"((a)[1]), "r"((a)[2]), "r"((a)[3]), "r"(b0), "r"(b1))

__device__ __forceinline__ uint32_t pack_bf2(float x, float y) {
    __nv_bfloat16 hx = __float2bfloat16_rn(x), hy = __float2bfloat16_rn(y);
    return (uint32_t)__bfloat16_as_ushort(hx) | ((uint32_t)__bfloat16_as_ushort(hy) << 16);
}
__device__ __forceinline__ void split4(float4 v, uint2& hi, uint2& lo) {
    __nv_bfloat16 h0 = __float2bfloat16_rn(v.x), h1 = __float2bfloat16_rn(v.y);
    __nv_bfloat16 h2 = __float2bfloat16_rn(v.z), h3 = __float2bfloat16_rn(v.w);
    hi.x = (uint32_t)__bfloat16_as_ushort(h0) | ((uint32_t)__bfloat16_as_ushort(h1) << 16);
    hi.y = (uint32_t)__bfloat16_as_ushort(h2) | ((uint32_t)__bfloat16_as_ushort(h3) << 16);
    lo.x = pack_bf2(v.x - __bfloat162float(h0), v.y - __bfloat162float(h1));
    lo.y = pack_bf2(v.z - __bfloat162float(h2), v.w - __bfloat162float(h3));
}

// ---------------- CSR construction ----------------
__global__ void k_hist(const int* __restrict__ ei, int e) {
    int i = blockIdx.x * blockDim.x + threadIdx.x;
    if (i < e) atomicAdd(&g_deg[__ldg(ei + e + i)], 1);
}
__global__ void k_scan(int n) {
    __shared__ int wsum[32];
    __shared__ int sbase;
    int lane = threadIdx.x & 31, wid = threadIdx.x >> 5;
    if (threadIdx.x == 0) sbase = 0;
    __syncthreads();
    for (int start = 0; start < n; start += 1024) {
        int i = start + threadIdx.x;
        int v = (i < n) ? g_deg[i] : 0;
        int s = v;
        #pragma unroll
        for (int o = 1; o < 32; o <<= 1) {
            int t = __shfl_up_sync(0xffffffffu, s, o);
            if (lane >= o) s += t;
        }
        if (lane == 31) wsum[wid] = s;
        __syncthreads();
        if (wid == 0) {
            int ws = wsum[lane];
            #pragma unroll
            for (int o = 1; o < 32; o <<= 1) {
                int t = __shfl_up_sync(0xffffffffu, ws, o);
                if (lane >= o) ws += t;
            }
            wsum[lane] = ws;
        }
        __syncthreads();
        int woff = (wid == 0) ? 0 : wsum[wid - 1];
        int excl = sbase + woff + s - v;
        if (i < n) { g_off[i] = excl; g_cur[i] = excl; }
        int total = wsum[31];
        __syncthreads();
        if (threadIdx.x == 0) sbase += total;
        __syncthreads();
    }
    if (threadIdx.x == 0) g_off[n] = sbase;
}
__global__ void k_scatter(const int* __restrict__ ei, int e) {
    int i = blockIdx.x * blockDim.x + threadIdx.x;
    if (i < e) {
        int dst = __ldg(ei + e + i);
        int p = atomicAdd(&g_cur[dst], 1);
        g_src[p] = __ldg(ei + i);
    }
}

// ---------------- merged per-layer weight split ----------------
__global__ void k_wsplit4(const float* __restrict__ W0, const float* __restrict__ W1,
                          const float* __restrict__ W2, const float* __restrict__ W3) {
    int gid = blockIdx.x * blockDim.x + threadIdx.x;
    if (gid >= 4 * 768 * 128) return;
    int l = gid / (768 * 128), idx = gid % (768 * 128);
    const float* Wg = (l == 0) ? W0 : (l == 1) ? W1 : (l == 2) ? W2 : W3;
    int n = idx / 768, k = idx - n * 768;
    int h = k >> 7, kk = k & 127;
    float v = Wg[h * 16384 + n * 128 + kk];
    __nv_bfloat16 hi = __float2bfloat16_rn(v);
    g_Bh[l][idx] = hi;
    g_Bl[l][idx] = __float2bfloat16_rn(v - __bfloat162float(hi));
}

// ---------------- input layer ----------------
__global__ void k_x0(const float* __restrict__ pos, const float* __restrict__ nrm,
                     const float* __restrict__ w1, const float* __restrict__ b1, int n) {
    int gid = blockIdx.x * blockDim.x + threadIdx.x;
    if (gid >= n * 128) return;
    int i = gid >> 7, d = gid & 127;
    const float* wr = w1 + d * 6;
    float a = b1[d];
    a = fmaf(pos[i * 3 + 0], wr[0], a);
    a = fmaf(pos[i * 3 + 1], wr[1], a);
    a = fmaf(pos[i * 3 + 2], wr[2], a);
    a = fmaf(nrm[i * 3 + 0], wr[3], a);
    a = fmaf(nrm[i * 3 + 1], wr[4], a);
    a = fmaf(nrm[i * 3 + 2], wr[5], a);
    g_x0[(size_t)i * 128 + d] = fmaxf(a, 0.f);
}

// ---------------- t = x @ u.T (standalone; layer 1 only) ----------------
__global__ void k_t(int sel, const float* __restrict__ u, int n) {
    int gw = (blockIdx.x * blockDim.x + threadIdx.x) >> 5;
    int lane = threadIdx.x & 31;
    if (gw >= n) return;
    const float* x = sel ? g_x1 : g_x0;
    float4 xv = *(const float4*)(x + (size_t)gw * 128 + lane * 4);
    float a0, a1, a2, a3, a4, a5;
    {
        float4 w;
        w = *(const float4*)(u + 0 * 128 + lane * 4); a0 = xv.x*w.x + xv.y*w.y + xv.z*w.z + xv.w*w.w;
        w = *(const float4*)(u + 1 * 128 + lane * 4); a1 = xv.x*w.x + xv.y*w.y + xv.z*w.z + xv.w*w.w;
        w = *(const float4*)(u + 2 * 128 + lane * 4); a2 = xv.x*w.x + xv.y*w.y + xv.z*w.z + xv.w*w.w;
        w = *(const float4*)(u + 3 * 128 + lane * 4); a3 = xv.x*w.x + xv.y*w.y + xv.z*w.z + xv.w*w.w;
        w = *(const float4*)(u + 4 * 128 + lane * 4); a4 = xv.x*w.x + xv.y*w.y + xv.z*w.z + xv.w*w.w;
        w = *(const float4*)(u + 5 * 128 + lane * 4); a5 = xv.x*w.x + xv.y*w.y + xv.z*w.z + xv.w*w.w;
    }
    #pragma unroll
    for (int o = 16; o; o >>= 1) {
        a0 += __shfl_xor_sync(0xffffffffu, a0, o);
        a1 += __shfl_xor_sync(0xffffffffu, a1, o);
        a2 += __shfl_xor_sync(0xffffffffu, a2, o);
        a3 += __shfl_xor_sync(0xffffffffu, a3, o);
        a4 += __shfl_xor_sync(0xffffffffu, a4, o);
        a5 += __shfl_xor_sync(0xffffffffu, a5, o);
    }
    if (lane == 0) {
        float* tp = g_t + (size_t)gw * 8;
        tp[0] = a0; tp[1] = a1; tp[2] = a2; tp[3] = a3; tp[4] = a4; tp[5] = a5;
        tp[6] = 0.f; tp[7] = 0.f;
    }
}

// ---------------- fused edge softmax + aggregation (warp per dst node) ----------------
#define AGG_FMA(q0, q1, q2, q3, q4, q5, xv)                                                      \
    do {                                                                                         \
        a0.x = fmaf(q0, xv.x, a0.x); a0.y = fmaf(q0, xv.y, a0.y);                                \
        a0.z = fmaf(q0, xv.z, a0.z); a0.w = fmaf(q0, xv.w, a0.w);                                \
        a1.x = fmaf(q1, xv.x, a1.x); a1.y = fmaf(q1, xv.y, a1.y);                                \
        a1.z = fmaf(q1, xv.z, a1.z); a1.w = fmaf(q1, xv.w, a1.w);                                \
        a2.x = fmaf(q2, xv.x, a2.x); a2.y = fmaf(q2, xv.y, a2.y);                                \
        a2.z = fmaf(q2, xv.z, a2.z); a2.w = fmaf(q2, xv.w, a2.w);                                \
        a3.x = fmaf(q3, xv.x, a3.x); a3.y = fmaf(q3, xv.y, a3.y);                                \
        a3.z = fmaf(q3, xv.z, a3.z); a3.w = fmaf(q3, xv.w, a3.w);                                \
        a4.x = fmaf(q4, xv.x, a4.x); a4.y = fmaf(q4, xv.y, a4.y);                                \
        a4.z = fmaf(q4, xv.z, a4.z); a4.w = fmaf(q4, xv.w, a4.w);                                \
        a5.x = fmaf(q5, xv.x, a5.x); a5.y = fmaf(q5, xv.y, a5.y);                                \
        a5.z = fmaf(q5, xv.z, a5.z); a5.w = fmaf(q5, xv.w, a5.w);                                \
    } while (0)

__global__ void __launch_bounds__(256) k_agg(int sel, const float* __restrict__ cvec, int n) {
    __shared__ float sq[8][32][8];   // [warp][edge][head(6)+pad]
    __shared__ int   ssrc[8][32];

    int w = threadIdx.x >> 5;
    int gw = (blockIdx.x * blockDim.x + threadIdx.x) >> 5;
    int lane = threadIdx.x & 31;
    if (gw >= n) return;
    const float* x = sel ? g_x1 : g_x0;
    int beg = g_off[gw], end = g_off[gw + 1];
    float invdeg = 1.f / fmaxf((float)(end - beg), 1.f);

    float4 td0 = *(const float4*)&g_t[(size_t)gw * 8];
    float4 td1 = *(const float4*)&g_t[(size_t)gw * 8 + 4];
    float bb0 = cvec[0] - td0.x, bb1 = cvec[1] - td0.y, bb2 = cvec[2] - td0.z;
    float bb3 = cvec[3] - td0.w, bb4 = cvec[4] - td1.x, bb5 = cvec[5] - td1.y;

    float4 a0 = make_float4(0,0,0,0), a1 = a0, a2 = a0, a3 = a0, a4 = a0, a5 = a0;

    for (int base = beg; base < end; base += 32) {
        int cnt = min(32, end - base);
        if (lane < cnt) {
            int s = g_src[base + lane];
            ssrc[w][lane] = s;
            float4 ts0 = *(const float4*)&g_t[(size_t)s * 8];
            float4 ts1 = *(const float4*)&g_t[(size_t)s * 8 + 4];
            float s0 = ts0.x + bb0, s1 = ts0.y + bb1, s2 = ts0.z + bb2;
            float s3 = ts0.w + bb3, s4 = ts1.x + bb4, s5 = ts1.y + bb5;
            float mx = fmaxf(fmaxf(fmaxf(s0, s1), fmaxf(s2, s3)), fmaxf(s4, s5));
            float e0 = __expf(s0 - mx), e1 = __expf(s1 - mx), e2 = __expf(s2 - mx);
            float e3 = __expf(s3 - mx), e4 = __expf(s4 - mx), e5 = __expf(s5 - mx);
            float inv = __fdividef(invdeg, e0 + e1 + e2 + e3 + e4 + e5);
            *(float4*)&sq[w][lane][0] = make_float4(e0 * inv, e1 * inv, e2 * inv, e3 * inv);
            *(float2*)&sq[w][lane][4] = make_float2(e4 * inv, e5 * inv);
        }
        __syncwarp();
        int j = 0;
        for (; j + 4 <= cnt; j += 4) {
            int sA = ssrc[w][j], sB = ssrc[w][j + 1], sC = ssrc[w][j + 2], sD = ssrc[w][j + 3];
            float4 xvA = *(const float4*)(x + (size_t)sA * 128 + lane * 4);
            float4 xvB = *(const float4*)(x + (size_t)sB * 128 + lane * 4);
            float4 xvC = *(const float4*)(x + (size_t)sC * 128 + lane * 4);
            float4 xvD = *(const float4*)(x + (size_t)sD * 128 + lane * 4);
            float4 qa; float2 qb;
            qa = *(const float4*)&sq[w][j][0];     qb = *(const float2*)&sq[w][j][4];
            AGG_FMA(qa.x, qa.y, qa.z, qa.w, qb.x, qb.y, xvA);
            qa = *(const float4*)&sq[w][j + 1][0]; qb = *(const float2*)&sq[w][j + 1][4];
            AGG_FMA(qa.x, qa.y, qa.z, qa.w, qb.x, qb.y, xvB);
            qa = *(const float4*)&sq[w][j + 2][0]; qb = *(const float2*)&sq[w][j + 2][4];
            AGG_FMA(qa.x, qa.y, qa.z, qa.w, qb.x, qb.y, xvC);
            qa = *(const float4*)&sq[w][j + 3][0]; qb = *(const float2*)&sq[w][j + 3][4];
            AGG_FMA(qa.x, qa.y, qa.z, qa.w, qb.x, qb.y, xvD);
        }
        for (; j < cnt; j++) {
            int s = ssrc[w][j];
            float4 qa = *(const float4*)&sq[w][j][0];
            float2 qb = *(const float2*)&sq[w][j][4];
            float4 xv = *(const float4*)(x + (size_t)s * 128 + lane * 4);
            AGG_FMA(qa.x, qa.y, qa.z, qa.w, qb.x, qb.y, xv);
        }
        __syncwarp();
    }

    size_t obase = (size_t)gw * 768 + lane * 4;
    uint2 hi, lo;
    split4(a0, hi, lo); *(uint2*)(g_Ah + obase + 0 * 128) = hi; *(uint2*)(g_Al + obase + 0 * 128) = lo;
    split4(a1, hi, lo); *(uint2*)(g_Ah + obase + 1 * 128) = hi; *(uint2*)(g_Al + obase + 1 * 128) = lo;
    split4(a2, hi, lo); *(uint2*)(g_Ah + obase + 2 * 128) = hi; *(uint2*)(g_Al + obase + 2 * 128) = lo;
    split4(a3, hi, lo); *(uint2*)(g_Ah + obase + 3 * 128) = hi; *(uint2*)(g_Al + obase + 3 * 128) = lo;
    split4(a4, hi, lo); *(uint2*)(g_Ah + obase + 4 * 128) = hi; *(uint2*)(g_Al + obase + 4 * 128) = lo;
    split4(a5, hi, lo); *(uint2*)(g_Ah + obase + 5 * 128) = hi; *(uint2*)(g_Al + obase + 5 * 128) = lo;
}

// ---------------- GEMM + fused epilogue projection ----------------
// mode 0: plain; mode 1: t = x'@u_next.T -> g_t; mode 2: out = x'@w2.T + b2 -> outp
// (3-stage cp.async pipeline, CTA 128x128, BK=16, 48 chunks.)
#define LDP 24

__global__ void __launch_bounds__(256, 2) k_gemm_mma(int l, const float* __restrict__ bias,
                                                     int outsel, const float* __restrict__ uw,
                                                     int mode, const float* __restrict__ b2,
                                                     float* __restrict__ outp, int n) {
    __shared__ __nv_bfloat16 sm[3][2][2][128][LDP];
    __shared__ float su[128][6];     // staged projection weights: su[col][h]
    __shared__ float st[2][128][6];  // per-warpN projection partials

    const int tid = threadIdx.x;
    const int wid = tid >> 5, lane = tid & 31;
    const int warpM = wid & 3, warpN = wid >> 2;    // 4 x 2
    const int g = lane >> 2, tig = lane & 3;
    const int blockRow = blockIdx.x * 128;

    const int rowS = tid >> 1, halfS = tid & 1;
    const __nv_bfloat16* gBh = g_Bh[l];
    const __nv_bfloat16* gBl = g_Bl[l];

    float acc[2][8][4];
    #pragma unroll
    for (int mt = 0; mt < 2; mt++)
        #pragma unroll
        for (int nt = 0; nt < 8; nt++)
            #pragma unroll
            for (int j = 0; j < 4; j++) acc[mt][nt][j] = 0.f;

    const int lj = lane >> 3, lrr = lane & 7;
    const int lrow = (lj & 1) * 8 + lrr;
    const int lcol = (lj >> 1) * 8;

    auto stage_load = [&](int c, int st2) {
        int k0 = c * 16;
        cpa16(smem_u32(&sm[st2][0][0][rowS][halfS * 8]),
              g_Ah + (size_t)(blockRow + rowS) * 768 + k0 + halfS * 8);
        cpa16(smem_u32(&sm[st2][0][1][rowS][halfS * 8]),
              g_Al + (size_t)(blockRow + rowS) * 768 + k0 + halfS * 8);
        cpa16(smem_u32(&sm[st2][1][0][rowS][halfS * 8]),
              gBh + (size_t)rowS * 768 + k0 + halfS * 8);
        cpa16(smem_u32(&sm[st2][1][1][rowS][halfS * 8]),
              gBl + (size_t)rowS * 768 + k0 + halfS * 8);
        CP_COMMIT();
    };

    // 3-stage prologue: prefetch chunks 0 and 1
    stage_load(0, 0);
    stage_load(1, 1);

    if (mode) {
        int nh = (mode == 1) ? 6 : 3;
        for (int i = tid; i < 768; i += 256) {
            int col = i / 6, h = i - col * 6;
            su[col][h] = (h < nh) ? uw[h * 128 + col] : 0.f;
        }
    }

    int stg = 0;
    for (int c = 0; c < 48; c++) {
        if (c + 2 < 48) {
            stage_load(c + 2, (c + 2) % 3);
            asm volatile("cp.async.wait_group 2;");
        } else if (c + 1 < 48) {
            asm volatile("cp.async.wait_group 1;");
        } else {
            asm volatile("cp.async.wait_group 0;");
        }
        __syncthreads();

        uint32_t aF[2][2][4];
        #pragma unroll
        for (int s = 0; s < 2; s++)
            #pragma unroll
            for (int mt = 0; mt < 2; mt++)
                LDMX4(aF[s][mt], smem_u32(&sm[stg][0][s][warpM * 32 + mt * 16 + lrow][lcol]));
        #pragma unroll
        for (int ntp = 0; ntp < 4; ntp++) {
            uint32_t bh[4], bl[4];
            LDMX4(bh, smem_u32(&sm[stg][1][0][warpN * 64 + ntp * 16 + lrow][lcol]));
            LDMX4(bl, smem_u32(&sm[stg][1][1][warpN * 64 + ntp * 16 + lrow][lcol]));
            #pragma unroll
            for (int mt = 0; mt < 2; mt++) {
                float* dE = acc[mt][2 * ntp];
                float* dO = acc[mt][2 * ntp + 1];
                MMA_BF16(dE, aF[0][mt], bh[0], bh[2]);
                MMA_BF16(dE, aF[0][mt], bl[0], bl[2]);
                MMA_BF16(dE, aF[1][mt], bh[0], bh[2]);
                MMA_BF16(dO, aF[0][mt], bh[1], bh[3]);
                MMA_BF16(dO, aF[0][mt], bl[1], bl[3]);
                MMA_BF16(dO, aF[1][mt], bh[1], bh[3]);
            }
        }
        __syncthreads();
        stg = (stg + 1) % 3;
    }

    // ---- epilogue: bias + relu (+ projection partials) ----
    float* C = outsel ? g_x1 : g_x0;
    float tp[2][2][6];
    #pragma unroll
    for (int mt = 0; mt < 2; mt++)
        #pragma unroll
        for (int rr = 0; rr < 2; rr++)
            #pragma unroll
            for (int h = 0; h < 6; h++) tp[mt][rr][h] = 0.f;

    #pragma unroll
    for (int nt = 0; nt < 8; nt++) {
        int col = warpN * 64 + nt * 8 + tig * 2;
        float b0 = bias[col], b1 = bias[col + 1];
        float u0[6], u1[6];
        if (mode) {
            #pragma unroll
            for (int h = 0; h < 6; h++) { u0[h] = su[col][h]; u1[h] = su[col + 1][h]; }
        }
        #pragma unroll
        for (int mt = 0; mt < 2; mt++) {
            int r0 = blockRow + warpM * 32 + mt * 16 + g;
            float2 v0, v1;
            v0.x = fmaxf(acc[mt][nt][0] + b0, 0.f);
            v0.y = fmaxf(acc[mt][nt][1] + b1, 0.f);
            v1.x = fmaxf(acc[mt][nt][2] + b0, 0.f);
            v1.y = fmaxf(acc[mt][nt][3] + b1, 0.f);
            *(float2*)&C[(size_t)r0 * 128 + col] = v0;
            *(float2*)&C[(size_t)(r0 + 8) * 128 + col] = v1;
            if (mode) {
                #pragma unroll
                for (int h = 0; h < 6; h++) {
                    tp[mt][0][h] = fmaf(v0.x, u0[h], fmaf(v0.y, u1[h], tp[mt][0][h]));
                    tp[mt][1][h] = fmaf(v1.x, u0[h], fmaf(v1.y, u1[h], tp[mt][1][h]));
                }
            }
        }
    }

    if (mode) {
        #pragma unroll
        for (int mt = 0; mt < 2; mt++)
            #pragma unroll
            for (int rr = 0; rr < 2; rr++)
                #pragma unroll
                for (int h = 0; h < 6; h++) {
                    float v = tp[mt][rr][h];
                    v += __shfl_xor_sync(0xffffffffu, v, 1);
                    v += __shfl_xor_sync(0xffffffffu, v, 2);
                    tp[mt][rr][h] = v;
                }
        if (tig == 0) {
            #pragma unroll
            for (int mt = 0; mt < 2; mt++)
                #pragma unroll
                for (int rr = 0; rr < 2; rr++) {
                    int row = warpM * 32 + mt * 16 + rr * 8 + g;
                    #pragma unroll
                    for (int h = 0; h < 6; h++) st[warpN][row][h] = tp[mt][rr][h];
                }
        }
        __syncthreads();
        if (mode == 1) {
            // t store (+ zero pads)
            for (int i = tid; i < 768; i += 256) {
                int row = i / 6, h = i - row * 6;
                g_t[(size_t)(blockRow + row) * 8 + h] = st[0][row][h] + st[1][row][h];
            }
            for (int i = tid; i < 256; i += 256) {
                int row = i >> 1;
                g_t[(size_t)(blockRow + row) * 8 + 6 + (i & 1)] = 0.f;
            }
        } else {
            // out store: out[grow][h] = sum + b2[h], guarded (d_out is exactly n*3)
            for (int i = tid; i < 384; i += 256) {
                int row = i / 3, h = i - row * 3;
                int grow = blockRow + row;
                if (grow < n)
                    outp[(size_t)grow * 3 + h] = st[0][row][h] + st[1][row][h] + b2[h];
            }
        }
    }
}

// ---------------- launch ----------------
extern "C" void kernel_launch(void* const* d_in, const int* in_sizes, int n_in,
                              void* d_out, int out_size) {
    const float* pos = (const float*)d_in[0];
    const float* nrm = (const float*)d_in[1];
    const int*   ei  = (const int*)d_in[2];
    const float* w1  = (const float*)d_in[3];
    const float* b1  = (const float*)d_in[4];
    const float* w2  = (const float*)d_in[5];
    const float* b2  = (const float*)d_in[6];
    const float* Wg[4] = {(const float*)d_in[7],  (const float*)d_in[11],
                          (const float*)d_in[15], (const float*)d_in[19]};
    const float* u[4]  = {(const float*)d_in[8],  (const float*)d_in[12],
                          (const float*)d_in[16], (const float*)d_in[20]};
    const float* c[4]  = {(const float*)d_in[9],  (const float*)d_in[13],
                          (const float*)d_in[17], (const float*)d_in[21]};
    const float* bg[4] = {(const float*)d_in[10], (const float*)d_in[14],
                          (const float*)d_in[18], (const float*)d_in[22]};

    int n = in_sizes[0] / 3;   // 50000
    int e = in_sizes[2] / 2;   // 800000

    // CSR build (deg zeroed by capturable async memset)
    void* degp = nullptr;
    cudaGetSymbolAddress(&degp, g_deg);
    cudaMemsetAsync(degp, 0, (size_t)n * sizeof(int));
    k_hist<<<(e + 255) / 256, 256>>>(ei, e);
    k_scan<<<1, 1024>>>(n);
    k_scatter<<<(e + 255) / 256, 256>>>(ei, e);

    // merged weight hi/lo split (all 4 layers)
    k_wsplit4<<<(4 * 768 * 128 + 255) / 256, 256>>>(Wg[0], Wg[1], Wg[2], Wg[3]);

    // input layer
    k_x0<<<(n * 128 + 255) / 256, 256>>>(pos, nrm, w1, b1, n);

    // 4 feast layers (ping-pong x between g_x0 / g_x1)
    int sel = 0;
    int warp_blocks = (n * 32 + 255) / 256;
    int gemm_blocks = (n + 127) / 128;     // 391
    k_t<<<warp_blocks, 256>>>(0, u[0], n);
    for (int l = 0; l < 4; l++) {
        k_agg<<<warp_blocks, 256>>>(sel, c[l], n);
        if (l < 3) {
            k_gemm_mma<<<gemm_blocks, 256>>>(l, bg[l], 1 - sel, u[l + 1], 1, b2,
                                             (float*)d_out, n);
        } else {
            k_gemm_mma<<<gemm_blocks, 256>>>(l, bg[l], 1 - sel, w2, 2, b2,
                                             (float*)d_out, n);
        }
        sel = 1 - sel;
    }
}

// round 17
// speedup vs baseline: 1.0340x; 1.0113x over previous
#include <cuda_runtime.h>
#include <cuda_bf16.h>
#include <math.h>
#include <stdint.h>

// ---------------- static scratch (no allocations allowed) ----------------
#define MAXN   50048            // padded (391*128)
#define MAXE   800000

__device__ float g_x0[MAXN * 128];
__device__ float g_x1[MAXN * 128];
__device__ __nv_bfloat16 g_Ah[(size_t)MAXN * 768];   // agg hi split (bf16)
__device__ __nv_bfloat16 g_Al[(size_t)MAXN * 768];   // agg lo split
__device__ float g_t[MAXN * 8];          // [N,6] padded to 8
__device__ __nv_bfloat16 g_Bh[4][768 * 128];  // B split hi: [l][n*768+k]
__device__ __nv_bfloat16 g_Bl[4][768 * 128];  // B split lo
__device__ int   g_deg[MAXN];
__device__ int   g_off[MAXN + 1];
__device__ int   g_cur[MAXN];
__device__ int   g_src[MAXE];

// ---------------- helpers ----------------
__device__ __forceinline__ uint32_t smem_u32(const void* p) {
    uint32_t a;
    asm("{ .reg .u64 t; cvta.to.shared.u64 t, %1; cvt.u32.u64 %0, t; }" : "=r"(a) : "l"(p));
    return a;
}
__device__ __forceinline__ void cpa16(uint32_t dst, const void* src) {
    asm volatile("cp.async.cg.shared.global [%0], [%1], 16;" :: "r"(dst), "l"(src));
}
#define CP_COMMIT() asm volatile("cp.async.commit_group;")
#define LDMX4(r, addr)                                                          \
    asm volatile("ldmatrix.sync.aligned.m8n8.x4.shared.b16 {%0,%1,%2,%3}, [%4];"\
        : "=r"((r)[0]), "=r"((r)[1]), "=r"((r)[2]), "=r"((r)[3]) : "r"(addr))
#define MMA_BF16(d, a, b0, b1)                                                  \
    asm volatile("mma.sync.aligned.m16n8k16.row.col.f32.bf16.bf16.f32 "         \
        "{%0,%1,%2,%3}, {%4,%5,%6,%7}, {%8,%9}, {%0,%1,%2,%3};"                 \
        : "+f"((d)[0]), "+f"((d)[1]), "+f"((d)[2]), "+f"((d)[3])                \
        : "r"((a)[0]), "r"((a)[1]), "r"((a)[2]), "r"((a)[3]), "r"(b0), "r"(b1))

__device__ __forceinline__ uint32_t pack_bf2(float x, float y) {
    __nv_bfloat16 hx = __float2bfloat16_rn(x), hy = __float2bfloat16_rn(y);
    return (uint32_t)__bfloat16_as_ushort(hx) | ((uint32_t)__bfloat16_as_ushort(hy) << 16);
}
__device__ __forceinline__ void split4(float4 v, uint2& hi, uint2& lo) {
    __nv_bfloat16 h0 = __float2bfloat16_rn(v.x), h1 = __float2bfloat16_rn(v.y);
    __nv_bfloat16 h2 = __float2bfloat16_rn(v.z), h3 = __float2bfloat16_rn(v.w);
    hi.x = (uint32_t)__bfloat16_as_ushort(h0) | ((uint32_t)__bfloat16_as_ushort(h1) << 16);
    hi.y = (uint32_t)__bfloat16_as_ushort(h2) | ((uint32_t)__bfloat16_as_ushort(h3) << 16);
    lo.x = pack_bf2(v.x - __bfloat162float(h0), v.y - __bfloat162float(h1));
    lo.y = pack_bf2(v.z - __bfloat162float(h2), v.w - __bfloat162float(h3));
}

// ---------------- fused preamble 1: hist || x0 || wsplit ----------------
// blockIdx ranges: [0, histB) hist; [histB, histB+x0B) x0; rest wsplit.
__global__ void __launch_bounds__(256) k_pre1(const int* __restrict__ ei, int e,
                                              const float* __restrict__ pos,
                                              const float* __restrict__ nrm,
                                              const float* __restrict__ w1,
                                              const float* __restrict__ b1, int n,
                                              const float* __restrict__ W0,
                                              const float* __restrict__ W1w,
                                              const float* __restrict__ W2,
                                              const float* __restrict__ W3,
                                              int histB, int x0B) {
    int b = blockIdx.x;
    if (b < histB) {
        int i = b * 256 + threadIdx.x;
        if (i < e) atomicAdd(&g_deg[__ldg(ei + e + i)], 1);
    } else if (b < histB + x0B) {
        int gid = (b - histB) * 256 + threadIdx.x;
        if (gid >= n * 128) return;
        int i = gid >> 7, d = gid & 127;
        const float* wr = w1 + d * 6;
        float a = b1[d];
        a = fmaf(pos[i * 3 + 0], wr[0], a);
        a = fmaf(pos[i * 3 + 1], wr[1], a);
        a = fmaf(pos[i * 3 + 2], wr[2], a);
        a = fmaf(nrm[i * 3 + 0], wr[3], a);
        a = fmaf(nrm[i * 3 + 1], wr[4], a);
        a = fmaf(nrm[i * 3 + 2], wr[5], a);
        g_x0[(size_t)i * 128 + d] = fmaxf(a, 0.f);
    } else {
        int gid = (b - histB - x0B) * 256 + threadIdx.x;
        if (gid >= 4 * 768 * 128) return;
        int l = gid / (768 * 128), idx = gid % (768 * 128);
        const float* Wg = (l == 0) ? W0 : (l == 1) ? W1w : (l == 2) ? W2 : W3;
        int nn = idx / 768, k = idx - nn * 768;
        int h = k >> 7, kk = k & 127;
        float v = Wg[h * 16384 + nn * 128 + kk];
        __nv_bfloat16 hi = __float2bfloat16_rn(v);
        g_Bh[l][idx] = hi;
        g_Bl[l][idx] = __float2bfloat16_rn(v - __bfloat162float(hi));
    }
}

// ---------------- scan (single block) ----------------
__global__ void k_scan(int n) {
    __shared__ int wsum[32];
    __shared__ int sbase;
    int lane = threadIdx.x & 31, wid = threadIdx.x >> 5;
    if (threadIdx.x == 0) sbase = 0;
    __syncthreads();
    for (int start = 0; start < n; start += 1024) {
        int i = start + threadIdx.x;
        int v = (i < n) ? g_deg[i] : 0;
        int s = v;
        #pragma unroll
        for (int o = 1; o < 32; o <<= 1) {
            int t = __shfl_up_sync(0xffffffffu, s, o);
            if (lane >= o) s += t;
        }
        if (lane == 31) wsum[wid] = s;
        __syncthreads();
        if (wid == 0) {
            int ws = wsum[lane];
            #pragma unroll
            for (int o = 1; o < 32; o <<= 1) {
                int t = __shfl_up_sync(0xffffffffu, ws, o);
                if (lane >= o) ws += t;
            }
            wsum[lane] = ws;
        }
        __syncthreads();
        int woff = (wid == 0) ? 0 : wsum[wid - 1];
        int excl = sbase + woff + s - v;
        if (i < n) { g_off[i] = excl; g_cur[i] = excl; }
        int total = wsum[31];
        __syncthreads();
        if (threadIdx.x == 0) sbase += total;
        __syncthreads();
    }
    if (threadIdx.x == 0) g_off[n] = sbase;
}

// ---------------- fused preamble 2: scatter || layer-1 t ----------------
__global__ void __launch_bounds__(256) k_pre2(const int* __restrict__ ei, int e,
                                              const float* __restrict__ u, int n, int scatB) {
    int b = blockIdx.x;
    if (b < scatB) {
        int i = b * 256 + threadIdx.x;
        if (i < e) {
            int dst = __ldg(ei + e + i);
            int p = atomicAdd(&g_cur[dst], 1);
            g_src[p] = __ldg(ei + i);
        }
    } else {
        int gw = ((b - scatB) * 256 + threadIdx.x) >> 5;
        int lane = threadIdx.x & 31;
        if (gw >= n) return;
        const float* x = g_x0;
        float4 xv = *(const float4*)(x + (size_t)gw * 128 + lane * 4);
        float a0, a1, a2, a3, a4, a5;
        {
            float4 w;
            w = *(const float4*)(u + 0 * 128 + lane * 4); a0 = xv.x*w.x + xv.y*w.y + xv.z*w.z + xv.w*w.w;
            w = *(const float4*)(u + 1 * 128 + lane * 4); a1 = xv.x*w.x + xv.y*w.y + xv.z*w.z + xv.w*w.w;
            w = *(const float4*)(u + 2 * 128 + lane * 4); a2 = xv.x*w.x + xv.y*w.y + xv.z*w.z + xv.w*w.w;
            w = *(const float4*)(u + 3 * 128 + lane * 4); a3 = xv.x*w.x + xv.y*w.y + xv.z*w.z + xv.w*w.w;
            w = *(const float4*)(u + 4 * 128 + lane * 4); a4 = xv.x*w.x + xv.y*w.y + xv.z*w.z + xv.w*w.w;
            w = *(const float4*)(u + 5 * 128 + lane * 4); a5 = xv.x*w.x + xv.y*w.y + xv.z*w.z + xv.w*w.w;
        }
        #pragma unroll
        for (int o = 16; o; o >>= 1) {
            a0 += __shfl_xor_sync(0xffffffffu, a0, o);
            a1 += __shfl_xor_sync(0xffffffffu, a1, o);
            a2 += __shfl_xor_sync(0xffffffffu, a2, o);
            a3 += __shfl_xor_sync(0xffffffffu, a3, o);
            a4 += __shfl_xor_sync(0xffffffffu, a4, o);
            a5 += __shfl_xor_sync(0xffffffffu, a5, o);
        }
        if (lane == 0) {
            float* tp = g_t + (size_t)gw * 8;
            tp[0] = a0; tp[1] = a1; tp[2] = a2; tp[3] = a3; tp[4] = a4; tp[5] = a5;
            tp[6] = 0.f; tp[7] = 0.f;
        }
    }
}

// ---------------- fused edge softmax + aggregation (warp per dst node) ----------------
#define AGG_FMA(q0, q1, q2, q3, q4, q5, xv)                                                      \
    do {                                                                                         \
        a0.x = fmaf(q0, xv.x, a0.x); a0.y = fmaf(q0, xv.y, a0.y);                                \
        a0.z = fmaf(q0, xv.z, a0.z); a0.w = fmaf(q0, xv.w, a0.w);                                \
        a1.x = fmaf(q1, xv.x, a1.x); a1.y = fmaf(q1, xv.y, a1.y);                                \
        a1.z = fmaf(q1, xv.z, a1.z); a1.w = fmaf(q1, xv.w, a1.w);                                \
        a2.x = fmaf(q2, xv.x, a2.x); a2.y = fmaf(q2, xv.y, a2.y);                                \
        a2.z = fmaf(q2, xv.z, a2.z); a2.w = fmaf(q2, xv.w, a2.w);                                \
        a3.x = fmaf(q3, xv.x, a3.x); a3.y = fmaf(q3, xv.y, a3.y);                                \
        a3.z = fmaf(q3, xv.z, a3.z); a3.w = fmaf(q3, xv.w, a3.w);                                \
        a4.x = fmaf(q4, xv.x, a4.x); a4.y = fmaf(q4, xv.y, a4.y);                                \
        a4.z = fmaf(q4, xv.z, a4.z); a4.w = fmaf(q4, xv.w, a4.w);                                \
        a5.x = fmaf(q5, xv.x, a5.x); a5.y = fmaf(q5, xv.y, a5.y);                                \
        a5.z = fmaf(q5, xv.z, a5.z); a5.w = fmaf(q5, xv.w, a5.w);                                \
    } while (0)

__global__ void __launch_bounds__(256) k_agg(int sel, const float* __restrict__ cvec, int n) {
    __shared__ float sq[8][32][8];   // [warp][edge][head(6)+pad]
    __shared__ int   ssrc[8][32];

    int w = threadIdx.x >> 5;
    int gw = (blockIdx.x * blockDim.x + threadIdx.x) >> 5;
    int lane = threadIdx.x & 31;
    if (gw >= n) return;
    const float* x = sel ? g_x1 : g_x0;
    int beg = g_off[gw], end = g_off[gw + 1];
    float invdeg = 1.f / fmaxf((float)(end - beg), 1.f);

    float4 td0 = *(const float4*)&g_t[(size_t)gw * 8];
    float4 td1 = *(const float4*)&g_t[(size_t)gw * 8 + 4];
    float bb0 = cvec[0] - td0.x, bb1 = cvec[1] - td0.y, bb2 = cvec[2] - td0.z;
    float bb3 = cvec[3] - td0.w, bb4 = cvec[4] - td1.x, bb5 = cvec[5] - td1.y;

    float4 a0 = make_float4(0,0,0,0), a1 = a0, a2 = a0, a3 = a0, a4 = a0, a5 = a0;

    for (int base = beg; base < end; base += 32) {
        int cnt = min(32, end - base);
        if (lane < cnt) {
            int s = g_src[base + lane];
            ssrc[w][lane] = s;
            float4 ts0 = *(const float4*)&g_t[(size_t)s * 8];
            float4 ts1 = *(const float4*)&g_t[(size_t)s * 8 + 4];
            float s0 = ts0.x + bb0, s1 = ts0.y + bb1, s2 = ts0.z + bb2;
            float s3 = ts0.w + bb3, s4 = ts1.x + bb4, s5 = ts1.y + bb5;
            float mx = fmaxf(fmaxf(fmaxf(s0, s1), fmaxf(s2, s3)), fmaxf(s4, s5));
            float e0 = __expf(s0 - mx), e1 = __expf(s1 - mx), e2 = __expf(s2 - mx);
            float e3 = __expf(s3 - mx), e4 = __expf(s4 - mx), e5 = __expf(s5 - mx);
            float inv = __fdividef(invdeg, e0 + e1 + e2 + e3 + e4 + e5);
            *(float4*)&sq[w][lane][0] = make_float4(e0 * inv, e1 * inv, e2 * inv, e3 * inv);
            *(float2*)&sq[w][lane][4] = make_float2(e4 * inv, e5 * inv);
        }
        __syncwarp();
        int j = 0;
        for (; j + 4 <= cnt; j += 4) {
            int sA = ssrc[w][j], sB = ssrc[w][j + 1], sC = ssrc[w][j + 2], sD = ssrc[w][j + 3];
            float4 xvA = *(const float4*)(x + (size_t)sA * 128 + lane * 4);
            float4 xvB = *(const float4*)(x + (size_t)sB * 128 + lane * 4);
            float4 xvC = *(const float4*)(x + (size_t)sC * 128 + lane * 4);
            float4 xvD = *(const float4*)(x + (size_t)sD * 128 + lane * 4);
            float4 qa; float2 qb;
            qa = *(const float4*)&sq[w][j][0];     qb = *(const float2*)&sq[w][j][4];
            AGG_FMA(qa.x, qa.y, qa.z, qa.w, qb.x, qb.y, xvA);
            qa = *(const float4*)&sq[w][j + 1][0]; qb = *(const float2*)&sq[w][j + 1][4];
            AGG_FMA(qa.x, qa.y, qa.z, qa.w, qb.x, qb.y, xvB);
            qa = *(const float4*)&sq[w][j + 2][0]; qb = *(const float2*)&sq[w][j + 2][4];
            AGG_FMA(qa.x, qa.y, qa.z, qa.w, qb.x, qb.y, xvC);
            qa = *(const float4*)&sq[w][j + 3][0]; qb = *(const float2*)&sq[w][j + 3][4];
            AGG_FMA(qa.x, qa.y, qa.z, qa.w, qb.x, qb.y, xvD);
        }
        for (; j < cnt; j++) {
            int s = ssrc[w][j];
            float4 qa = *(const float4*)&sq[w][j][0];
            float2 qb = *(const float2*)&sq[w][j][4];
            float4 xv = *(const float4*)(x + (size_t)s * 128 + lane * 4);
            AGG_FMA(qa.x, qa.y, qa.z, qa.w, qb.x, qb.y, xv);
        }
        __syncwarp();
    }

    size_t obase = (size_t)gw * 768 + lane * 4;
    uint2 hi, lo;
    split4(a0, hi, lo); *(uint2*)(g_Ah + obase + 0 * 128) = hi; *(uint2*)(g_Al + obase + 0 * 128) = lo;
    split4(a1, hi, lo); *(uint2*)(g_Ah + obase + 1 * 128) = hi; *(uint2*)(g_Al + obase + 1 * 128) = lo;
    split4(a2, hi, lo); *(uint2*)(g_Ah + obase + 2 * 128) = hi; *(uint2*)(g_Al + obase + 2 * 128) = lo;
    split4(a3, hi, lo); *(uint2*)(g_Ah + obase + 3 * 128) = hi; *(uint2*)(g_Al + obase + 3 * 128) = lo;
    split4(a4, hi, lo); *(uint2*)(g_Ah + obase + 4 * 128) = hi; *(uint2*)(g_Al + obase + 4 * 128) = lo;
    split4(a5, hi, lo); *(uint2*)(g_Ah + obase + 5 * 128) = hi; *(uint2*)(g_Al + obase + 5 * 128) = lo;
}

// ---------------- GEMM + fused epilogue projection ----------------
// mode 0: plain; mode 1: t = x'@u_next.T -> g_t; mode 2: out = x'@w2.T + b2 -> outp
// (3-stage cp.async pipeline, CTA 128x128, BK=16, 48 chunks.)
#define LDP 24

__global__ void __launch_bounds__(256, 2) k_gemm_mma(int l, const float* __restrict__ bias,
                                                     int outsel, const float* __restrict__ uw,
                                                     int mode, const float* __restrict__ b2,
                                                     float* __restrict__ outp, int n) {
    __shared__ __nv_bfloat16 sm[3][2][2][128][LDP];
    __shared__ float su[128][6];     // staged projection weights: su[col][h]
    __shared__ float st[2][128][6];  // per-warpN projection partials

    const int tid = threadIdx.x;
    const int wid = tid >> 5, lane = tid & 31;
    const int warpM = wid & 3, warpN = wid >> 2;    // 4 x 2
    const int g = lane >> 2, tig = lane & 3;
    const int blockRow = blockIdx.x * 128;

    const int rowS = tid >> 1, halfS = tid & 1;
    const __nv_bfloat16* gBh = g_Bh[l];
    const __nv_bfloat16* gBl = g_Bl[l];

    float acc[2][8][4];
    #pragma unroll
    for (int mt = 0; mt < 2; mt++)
        #pragma unroll
        for (int nt = 0; nt < 8; nt++)
            #pragma unroll
            for (int j = 0; j < 4; j++) acc[mt][nt][j] = 0.f;

    const int lj = lane >> 3, lrr = lane & 7;
    const int lrow = (lj & 1) * 8 + lrr;
    const int lcol = (lj >> 1) * 8;

    auto stage_load = [&](int c, int st2) {
        int k0 = c * 16;
        cpa16(smem_u32(&sm[st2][0][0][rowS][halfS * 8]),
              g_Ah + (size_t)(blockRow + rowS) * 768 + k0 + halfS * 8);
        cpa16(smem_u32(&sm[st2][0][1][rowS][halfS * 8]),
              g_Al + (size_t)(blockRow + rowS) * 768 + k0 + halfS * 8);
        cpa16(smem_u32(&sm[st2][1][0][rowS][halfS * 8]),
              gBh + (size_t)rowS * 768 + k0 + halfS * 8);
        cpa16(smem_u32(&sm[st2][1][1][rowS][halfS * 8]),
              gBl + (size_t)rowS * 768 + k0 + halfS * 8);
        CP_COMMIT();
    };

    // 3-stage prologue: prefetch chunks 0 and 1
    stage_load(0, 0);
    stage_load(1, 1);

    if (mode) {
        int nh = (mode == 1) ? 6 : 3;
        for (int i = tid; i < 768; i += 256) {
            int col = i / 6, h = i - col * 6;
            su[col][h] = (h < nh) ? uw[h * 128 + col] : 0.f;
        }
    }

    int stg = 0;
    for (int c = 0; c < 48; c++) {
        if (c + 2 < 48) {
            stage_load(c + 2, (c + 2) % 3);
            asm volatile("cp.async.wait_group 2;");
        } else if (c + 1 < 48) {
            asm volatile("cp.async.wait_group 1;");
        } else {
            asm volatile("cp.async.wait_group 0;");
        }
        __syncthreads();

        uint32_t aF[2][2][4];
        #pragma unroll
        for (int s = 0; s < 2; s++)
            #pragma unroll
            for (int mt = 0; mt < 2; mt++)
                LDMX4(aF[s][mt], smem_u32(&sm[stg][0][s][warpM * 32 + mt * 16 + lrow][lcol]));
        #pragma unroll
        for (int ntp = 0; ntp < 4; ntp++) {
            uint32_t bh[4], bl[4];
            LDMX4(bh, smem_u32(&sm[stg][1][0][warpN * 64 + ntp * 16 + lrow][lcol]));
            LDMX4(bl, smem_u32(&sm[stg][1][1][warpN * 64 + ntp * 16 + lrow][lcol]));
            #pragma unroll
            for (int mt = 0; mt < 2; mt++) {
                float* dE = acc[mt][2 * ntp];
                float* dO = acc[mt][2 * ntp + 1];
                MMA_BF16(dE, aF[0][mt], bh[0], bh[2]);
                MMA_BF16(dE, aF[0][mt], bl[0], bl[2]);
                MMA_BF16(dE, aF[1][mt], bh[0], bh[2]);
                MMA_BF16(dO, aF[0][mt], bh[1], bh[3]);
                MMA_BF16(dO, aF[0][mt], bl[1], bl[3]);
                MMA_BF16(dO, aF[1][mt], bh[1], bh[3]);
            }
        }
        __syncthreads();
        stg = (stg + 1) % 3;
    }

    // ---- epilogue: bias + relu (+ projection partials) ----
    float* C = outsel ? g_x1 : g_x0;
    float tp[2][2][6];
    #pragma unroll
    for (int mt = 0; mt < 2; mt++)
        #pragma unroll
        for (int rr = 0; rr < 2; rr++)
            #pragma unroll
            for (int h = 0; h < 6; h++) tp[mt][rr][h] = 0.f;

    #pragma unroll
    for (int nt = 0; nt < 8; nt++) {
        int col = warpN * 64 + nt * 8 + tig * 2;
        float b0 = bias[col], b1 = bias[col + 1];
        float u0[6], u1[6];
        if (mode) {
            #pragma unroll
            for (int h = 0; h < 6; h++) { u0[h] = su[col][h]; u1[h] = su[col + 1][h]; }
        }
        #pragma unroll
        for (int mt = 0; mt < 2; mt++) {
            int r0 = blockRow + warpM * 32 + mt * 16 + g;
            float2 v0, v1;
            v0.x = fmaxf(acc[mt][nt][0] + b0, 0.f);
            v0.y = fmaxf(acc[mt][nt][1] + b1, 0.f);
            v1.x = fmaxf(acc[mt][nt][2] + b0, 0.f);
            v1.y = fmaxf(acc[mt][nt][3] + b1, 0.f);
            *(float2*)&C[(size_t)r0 * 128 + col] = v0;
            *(float2*)&C[(size_t)(r0 + 8) * 128 + col] = v1;
            if (mode) {
                #pragma unroll
                for (int h = 0; h < 6; h++) {
                    tp[mt][0][h] = fmaf(v0.x, u0[h], fmaf(v0.y, u1[h], tp[mt][0][h]));
                    tp[mt][1][h] = fmaf(v1.x, u0[h], fmaf(v1.y, u1[h], tp[mt][1][h]));
                }
            }
        }
    }

    if (mode) {
        #pragma unroll
        for (int mt = 0; mt < 2; mt++)
            #pragma unroll
            for (int rr = 0; rr < 2; rr++)
                #pragma unroll
                for (int h = 0; h < 6; h++) {
                    float v = tp[mt][rr][h];
                    v += __shfl_xor_sync(0xffffffffu, v, 1);
                    v += __shfl_xor_sync(0xffffffffu, v, 2);
                    tp[mt][rr][h] = v;
                }
        if (tig == 0) {
            #pragma unroll
            for (int mt = 0; mt < 2; mt++)
                #pragma unroll
                for (int rr = 0; rr < 2; rr++) {
                    int row = warpM * 32 + mt * 16 + rr * 8 + g;
                    #pragma unroll
                    for (int h = 0; h < 6; h++) st[warpN][row][h] = tp[mt][rr][h];
                }
        }
        __syncthreads();
        if (mode == 1) {
            for (int i = tid; i < 768; i += 256) {
                int row = i / 6, h = i - row * 6;
                g_t[(size_t)(blockRow + row) * 8 + h] = st[0][row][h] + st[1][row][h];
            }
            for (int i = tid; i < 256; i += 256) {
                int row = i >> 1;
                g_t[(size_t)(blockRow + row) * 8 + 6 + (i & 1)] = 0.f;
            }
        } else {
            for (int i = tid; i < 384; i += 256) {
                int row = i / 3, h = i - row * 3;
                int grow = blockRow + row;
                if (grow < n)
                    outp[(size_t)grow * 3 + h] = st[0][row][h] + st[1][row][h] + b2[h];
            }
        }
    }
}

// ---------------- launch ----------------
extern "C" void kernel_launch(void* const* d_in, const int* in_sizes, int n_in,
                              void* d_out, int out_size) {
    const float* pos = (const float*)d_in[0];
    const float* nrm = (const float*)d_in[1];
    const int*   ei  = (const int*)d_in[2];
    const float* w1  = (const float*)d_in[3];
    const float* b1  = (const float*)d_in[4];
    const float* w2  = (const float*)d_in[5];
    const float* b2  = (const float*)d_in[6];
    const float* Wg[4] = {(const float*)d_in[7],  (const float*)d_in[11],
                          (const float*)d_in[15], (const float*)d_in[19]};
    const float* u[4]  = {(const float*)d_in[8],  (const float*)d_in[12],
                          (const float*)d_in[16], (const float*)d_in[20]};
    const float* c[4]  = {(const float*)d_in[9],  (const float*)d_in[13],
                          (const float*)d_in[17], (const float*)d_in[21]};
    const float* bg[4] = {(const float*)d_in[10], (const float*)d_in[14],
                          (const float*)d_in[18], (const float*)d_in[22]};

    int n = in_sizes[0] / 3;   // 50000
    int e = in_sizes[2] / 2;   // 800000

    // deg zeroed by capturable async memset
    void* degp = nullptr;
    cudaGetSymbolAddress(&degp, g_deg);
    cudaMemsetAsync(degp, 0, (size_t)n * sizeof(int));

    // fused preamble 1: hist || x0 || wsplit
    int histB = (e + 255) / 256;
    int x0B = (n * 128 + 255) / 256;
    int wsB = (4 * 768 * 128 + 255) / 256;
    k_pre1<<<histB + x0B + wsB, 256>>>(ei, e, pos, nrm, w1, b1, n,
                                       Wg[0], Wg[1], Wg[2], Wg[3], histB, x0B);

    k_scan<<<1, 1024>>>(n);

    // fused preamble 2: scatter || layer-1 t
    int scatB = (e + 255) / 256;
    int tB = (n * 32 + 255) / 256;
    k_pre2<<<scatB + tB, 256>>>(ei, e, u[0], n, scatB);

    // 4 feast layers (ping-pong x between g_x0 / g_x1)
    int sel = 0;
    int warp_blocks = (n * 32 + 255) / 256;
    int gemm_blocks = (n + 127) / 128;     // 391
    for (int l = 0; l < 4; l++) {
        k_agg<<<warp_blocks, 256>>>(sel, c[l], n);
        if (l < 3) {
            k_gemm_mma<<<gemm_blocks, 256>>>(l, bg[l], 1 - sel, u[l + 1], 1, b2,
                                             (float*)d_out, n);
        } else {
            k_gemm_mma<<<gemm_blocks, 256>>>(l, bg[l], 1 - sel, w2, 2, b2,
                                             (float*)d_out, n);
        }
        sel = 1 - sel;
    }
}